// round 5
// baseline (speedup 1.0000x reference)
#include <cuda_runtime.h>
#include <cuda_bf16.h>
#include <cstdint>
#include <math.h>

using bf16 = __nv_bfloat16;
#define BB 2
#define SSZ 256

// scratch (device globals; no cudaMalloc allowed)
__device__ bf16  g_left [(size_t)BB * 128 * SSZ * SSZ];  // [b][h][i][k]
__device__ bf16  g_right[(size_t)BB * 128 * SSZ * SSZ];  // [b][h][j][k]
__device__ bf16  g_tri  [(size_t)BB * 128 * SSZ * SSZ];  // [b][h][i][j]
__device__ float g_gate [(size_t)BB * SSZ * SSZ * 128];  // [b][i][j][h]
__device__ bf16  g_whi[6 * 16384];  // 0:left 1:right 2:lg 3:rg 4:og 5:w_out
__device__ bf16  g_wlo[6 * 16384];

static __device__ __forceinline__ uint32_t cvta_s(const void* p) {
    return (uint32_t)__cvta_generic_to_shared(p);
}
static __device__ __forceinline__ void ldsm4(uint32_t a, uint32_t& r0, uint32_t& r1,
                                             uint32_t& r2, uint32_t& r3) {
    asm volatile("ldmatrix.sync.aligned.m8n8.x4.shared.b16 {%0,%1,%2,%3},[%4];"
                 : "=r"(r0), "=r"(r1), "=r"(r2), "=r"(r3) : "r"(a));
}
static __device__ __forceinline__ void mma16816(float* c, const uint32_t* a,
                                                const uint32_t* b) {
    asm volatile(
        "mma.sync.aligned.m16n8k16.row.col.f32.bf16.bf16.f32 "
        "{%0,%1,%2,%3},{%4,%5,%6,%7},{%8,%9},{%0,%1,%2,%3};"
        : "+f"(c[0]), "+f"(c[1]), "+f"(c[2]), "+f"(c[3])
        : "r"(a[0]), "r"(a[1]), "r"(a[2]), "r"(a[3]), "r"(b[0]), "r"(b[1]));
}
template <int SB>  // SB = smem row stride in bytes
static __device__ __forceinline__ void load_a(uint32_t base, int m0, int k0, int lane,
                                              uint32_t a[2][4]) {
#pragma unroll
    for (int fm = 0; fm < 2; ++fm) {
        int row = m0 + fm * 16 + (lane & 15), col = k0 + ((lane >> 4) << 3);
        ldsm4(base + row * SB + col * 2, a[fm][0], a[fm][1], a[fm][2], a[fm][3]);
    }
}
template <int SB>
static __device__ __forceinline__ void load_b(uint32_t base, int n0, int k0, int lane,
                                              uint32_t b[8][2]) {
#pragma unroll
    for (int q = 0; q < 4; ++q) {
        int row = n0 + q * 16 + (lane & 7) + ((lane >> 4) << 3);
        int col = k0 + (((lane >> 3) & 1) << 3);
        ldsm4(base + row * SB + col * 2, b[2 * q][0], b[2 * q][1],
              b[2 * q + 1][0], b[2 * q + 1][1]);
    }
}
// one full K=128 pass of a 128x128 tile GEMM, warp layout 4x2 (32m x 64n)
static __device__ __forceinline__ void gemm128(uint32_t sA, uint32_t sB, int lane,
                                               int m0, int n0, float acc[2][8][4]) {
#pragma unroll
    for (int ks = 0; ks < 8; ++ks) {
        uint32_t a[2][4], b[8][2];
        load_a<272>(sA, m0, ks * 16, lane, a);
        load_b<272>(sB, n0, ks * 16, lane, b);
#pragma unroll
        for (int fm = 0; fm < 2; ++fm)
#pragma unroll
            for (int fn = 0; fn < 8; ++fn) mma16816(acc[fm][fn], a[fm], b[fn]);
    }
}
static __device__ __forceinline__ void gemm3(uint32_t sAh, uint32_t sAl, uint32_t sBh,
                                             uint32_t sBl, int lane, int m0, int n0,
                                             float acc[2][8][4]) {
    gemm128(sAh, sBh, lane, m0, n0, acc);
    gemm128(sAh, sBl, lane, m0, n0, acc);
    gemm128(sAl, sBh, lane, m0, n0, acc);
}
static __device__ __forceinline__ float warpsum(float v) {
#pragma unroll
    for (int o = 16; o > 0; o >>= 1) v += __shfl_xor_sync(0xffffffffu, v, o);
    return v;
}
#define ZERO_ACC(acc)                                           \
    {                                                           \
        _Pragma("unroll") for (int z1 = 0; z1 < 2; ++z1)        \
            _Pragma("unroll") for (int z2 = 0; z2 < 8; ++z2)    \
                _Pragma("unroll") for (int z3 = 0; z3 < 4; ++z3)\
                    acc[z1][z2][z3] = 0.f;                      \
    }

// ---------------- K0 ----------------
__global__ void k0_prep(const float* wl, const float* wr, const float* wlg,
                        const float* wrg, const float* wog, const float* wout) {
    const float* srcs[6] = {wl, wr, wlg, wrg, wog, wout};
    const float* s = srcs[blockIdx.x];
    int base = blockIdx.x * 16384;
    for (int i = threadIdx.x; i < 16384; i += 256) {
        float v = s[i];
        bf16 h = __float2bfloat16(v);
        g_whi[base + i] = h;
        g_wlo[base + i] = __float2bfloat16(v - __bfloat162float(h));
    }
}

// ---------------- K1: LN + 5 projections + gating ----------------
#define K1_SMEM (69632 + 139264 + 512)
__global__ void __launch_bounds__(256, 1)
k1_proj(const float* __restrict__ x, const float* __restrict__ mask,
        const float* __restrict__ nw, const float* __restrict__ nb) {
    extern __shared__ char sm[];
    bf16* Ahi = (bf16*)sm;
    bf16* Alo = Ahi + 128 * 136;
    char* Wb = sm + 69632;
    float* msk = (float*)(sm + 69632 + 139264);
    const int tid = threadIdx.x, lane = tid & 31, wid = tid >> 5;
    const int kt = blockIdx.x, bi = blockIdx.y;
    const int b = bi >> 8, i = bi & 255, k0g = kt * 128;

    if (tid < 128) msk[tid] = mask[(size_t)bi * 256 + k0g + tid];
    const float4 nwv = reinterpret_cast<const float4*>(nw)[lane];
    const float4 nbv = reinterpret_cast<const float4*>(nb)[lane];
    for (int r = wid * 16; r < wid * 16 + 16; ++r) {
        const float4 v = reinterpret_cast<const float4*>(
            x + ((size_t)bi * 256 + k0g + r) * 128)[lane];
        float mu = warpsum(v.x + v.y + v.z + v.w) * 0.0078125f;
        float dx = v.x - mu, dy = v.y - mu, dz = v.z - mu, dw = v.w - mu;
        float rs = rsqrtf(warpsum(dx * dx + dy * dy + dz * dz + dw * dw) * 0.0078125f + 1e-5f);
        float f0 = dx * rs * nwv.x + nbv.x, f1 = dy * rs * nwv.y + nbv.y;
        float f2 = dz * rs * nwv.z + nbv.z, f3 = dw * rs * nwv.w + nbv.w;
        bf16 h0 = __float2bfloat16(f0), h1 = __float2bfloat16(f1);
        bf16 h2 = __float2bfloat16(f2), h3 = __float2bfloat16(f3);
        int c = lane * 4;
        __nv_bfloat162* ph = (__nv_bfloat162*)(Ahi + r * 136 + c);
        ph[0] = __nv_bfloat162(h0, h1); ph[1] = __nv_bfloat162(h2, h3);
        __nv_bfloat162* pl = (__nv_bfloat162*)(Alo + r * 136 + c);
        pl[0] = __nv_bfloat162(__float2bfloat16(f0 - __bfloat162float(h0)),
                               __float2bfloat16(f1 - __bfloat162float(h1)));
        pl[1] = __nv_bfloat162(__float2bfloat16(f2 - __bfloat162float(h2)),
                               __float2bfloat16(f3 - __bfloat162float(h3)));
    }
    __syncthreads();
    const uint32_t sAh = cvta_s(Ahi), sAl = cvta_s(Alo);
    const int wm = wid & 3, wn = wid >> 2;
    bf16* W0 = (bf16*)Wb; bf16* W1 = W0 + 128 * 136;
    bf16* W2 = W1 + 128 * 136; bf16* W3 = W2 + 128 * 136;

#pragma unroll 1
    for (int pass = 0; pass < 2; ++pass) {
        const bf16* srcs[4] = {g_whi + pass * 16384, g_wlo + pass * 16384,
                               g_whi + (2 + pass) * 16384, g_wlo + (2 + pass) * 16384};
        bf16* dsts[4] = {W0, W1, W2, W3};
#pragma unroll
        for (int mtx = 0; mtx < 4; ++mtx)
#pragma unroll
            for (int it = 0; it < 8; ++it) {
                int idx = it * 256 + tid, row = idx >> 4, c8 = (idx & 15) << 3;
                *(uint4*)(dsts[mtx] + row * 136 + c8) =
                    *(const uint4*)(srcs[mtx] + row * 128 + c8);
            }
        __syncthreads();
        float accP[2][8][4], accG[2][8][4];
        ZERO_ACC(accP); ZERO_ACC(accG);
        gemm3(sAh, sAl, cvta_s(W0), cvta_s(W1), lane, wm * 32, wn * 64, accP);
        gemm3(sAh, sAl, cvta_s(W2), cvta_s(W3), lane, wm * 32, wn * 64, accG);
        __syncthreads();
        bf16* S2 = W0;  // [h][k] stride 136
#pragma unroll
        for (int fm = 0; fm < 2; ++fm)
#pragma unroll
            for (int fn = 0; fn < 8; ++fn)
#pragma unroll
                for (int ci = 0; ci < 4; ++ci) {
                    int row = wm * 32 + fm * 16 + (lane >> 2) + ((ci >> 1) << 3);
                    int col = wn * 64 + fn * 8 + ((lane & 3) << 1) + (ci & 1);
                    float sg = 1.0f / (1.0f + expf(-accG[fm][fn][ci]));
                    S2[col * 136 + row] = __float2bfloat16(accP[fm][fn][ci] * msk[row] * sg);
                }
        __syncthreads();
        bf16* dst = pass == 0 ? g_left : g_right;
#pragma unroll
        for (int it = 0; it < 8; ++it) {
            int idx = it * 256 + tid, h = idx >> 4, c8 = (idx & 15) << 3;
            *(uint4*)&dst[(((size_t)b * 128 + h) * 256 + i) * 256 + k0g + c8] =
                *(const uint4*)(S2 + h * 136 + c8);
        }
        __syncthreads();
    }
    // out-gate pass
#pragma unroll
    for (int it = 0; it < 8; ++it) {
        int idx = it * 256 + tid, row = idx >> 4, c8 = (idx & 15) << 3;
        *(uint4*)(W0 + row * 136 + c8) = *(const uint4*)(g_whi + 4 * 16384 + row * 128 + c8);
        *(uint4*)(W1 + row * 136 + c8) = *(const uint4*)(g_wlo + 4 * 16384 + row * 128 + c8);
    }
    __syncthreads();
    float accG[2][8][4];
    ZERO_ACC(accG);
    gemm3(sAh, sAl, cvta_s(W0), cvta_s(W1), lane, wm * 32, wn * 64, accG);
    __syncthreads();
    float* Sf = (float*)Wb;  // [k][h] stride 132
#pragma unroll
    for (int fm = 0; fm < 2; ++fm)
#pragma unroll
        for (int fn = 0; fn < 8; ++fn)
#pragma unroll
            for (int ci = 0; ci < 4; ++ci) {
                int row = wm * 32 + fm * 16 + (lane >> 2) + ((ci >> 1) << 3);
                int col = wn * 64 + fn * 8 + ((lane & 3) << 1) + (ci & 1);
                Sf[row * 132 + col] = 1.0f / (1.0f + expf(-accG[fm][fn][ci]));
            }
    __syncthreads();
#pragma unroll
    for (int it = 0; it < 16; ++it) {
        int idx = it * 256 + tid, row = idx >> 5, c4 = (idx & 31) << 2;
        *(float4*)&g_gate[((size_t)bi * 256 + k0g + row) * 128 + c4] =
            *(const float4*)(Sf + row * 132 + c4);
    }
}

// ---------------- K2: batched 256^3 bf16 NT GEMM ----------------
#define K2_SMEM (2 * 128 * 72 * 2)
__global__ void __launch_bounds__(256, 1) k2_tri() {
    extern __shared__ char sm[];
    bf16* Ls = (bf16*)sm;
    bf16* Rs = Ls + 128 * 72;
    const int tid = threadIdx.x, lane = tid & 31, wid = tid >> 5;
    const int wm = wid & 3, wn = wid >> 2;
    const int p = blockIdx.y, ti = blockIdx.x >> 1, tj = blockIdx.x & 1;
    const bf16* Lg = g_left + (size_t)p * 65536 + (size_t)ti * 128 * 256;
    const bf16* Rg = g_right + (size_t)p * 65536 + (size_t)tj * 128 * 256;
    float acc[2][8][4];
    ZERO_ACC(acc);
    const uint32_t sL = cvta_s(Ls), sR = cvta_s(Rs);
#pragma unroll 1
    for (int kc = 0; kc < 4; ++kc) {
#pragma unroll
        for (int it = 0; it < 4; ++it) {
            int idx = it * 256 + tid, row = idx >> 3, c8 = (idx & 7) << 3;
            *(uint4*)(Ls + row * 72 + c8) = *(const uint4*)(Lg + row * 256 + kc * 64 + c8);
            *(uint4*)(Rs + row * 72 + c8) = *(const uint4*)(Rg + row * 256 + kc * 64 + c8);
        }
        __syncthreads();
#pragma unroll
        for (int ks = 0; ks < 4; ++ks) {
            uint32_t a[2][4], b[8][2];
            load_a<144>(sL, wm * 32, ks * 16, lane, a);
            load_b<144>(sR, wn * 64, ks * 16, lane, b);
#pragma unroll
            for (int fm = 0; fm < 2; ++fm)
#pragma unroll
                for (int fn = 0; fn < 8; ++fn) mma16816(acc[fm][fn], a[fm], b[fn]);
        }
        __syncthreads();
    }
    bf16* Og = g_tri + (size_t)p * 65536 + (size_t)ti * 128 * 256 + tj * 128;
#pragma unroll
    for (int fm = 0; fm < 2; ++fm)
#pragma unroll
        for (int fn = 0; fn < 8; ++fn)
#pragma unroll
            for (int cp = 0; cp < 2; ++cp) {
                int row = wm * 32 + fm * 16 + (lane >> 2) + cp * 8;
                int col = wn * 64 + fn * 8 + ((lane & 3) << 1);
                *(__nv_bfloat162*)&Og[row * 256 + col] =
                    __nv_bfloat162(__float2bfloat16(acc[fm][fn][2 * cp]),
                                   __float2bfloat16(acc[fm][fn][2 * cp + 1]));
            }
}

// ---------------- K3: LN over h + gate + output GEMM ----------------
#define K3_SMEM (5 * 128 * 136 * 2)
__global__ void __launch_bounds__(256, 1)
k3_out(const float* __restrict__ onw, const float* __restrict__ onb,
       float* __restrict__ out) {
    extern __shared__ char sm[];
    bf16* T = (bf16*)sm;             // [h][j] stride 136
    bf16* Ahi = T + 128 * 136;       // [j][h] stride 136
    bf16* Alo = Ahi + 128 * 136;
    bf16* Whi = Alo + 128 * 136;
    bf16* Wlo = Whi + 128 * 136;
    const int tid = threadIdx.x, lane = tid & 31, wid = tid >> 5;
    const int jt = blockIdx.x, bi = blockIdx.y;
    const int b = bi >> 8, i = bi & 255, j0g = jt * 128;
#pragma unroll
    for (int it = 0; it < 8; ++it) {
        int idx = it * 256 + tid, h = idx >> 4, c8 = (idx & 15) << 3;
        *(uint4*)(T + h * 136 + c8) =
            *(const uint4*)&g_tri[(((size_t)b * 128 + h) * 256 + i) * 256 + j0g + c8];
        *(uint4*)(Whi + h * 136 + c8) = *(const uint4*)(g_whi + 5 * 16384 + h * 128 + c8);
        *(uint4*)(Wlo + h * 136 + c8) = *(const uint4*)(g_wlo + 5 * 16384 + h * 128 + c8);
    }
    __syncthreads();
    {
        const int j = tid >> 1, h0 = (tid & 1) * 64;
        float s1 = 0.f, s2 = 0.f;
#pragma unroll 8
        for (int h = h0; h < h0 + 64; ++h) {
            float f = __bfloat162float(T[h * 136 + j]);
            s1 += f; s2 += f * f;
        }
        s1 += __shfl_xor_sync(0xffffffffu, s1, 1);
        s2 += __shfl_xor_sync(0xffffffffu, s2, 1);
        float mu = s1 * 0.0078125f;
        float var = s2 * 0.0078125f - mu * mu;
        float rs = rsqrtf(fmaxf(var, 0.f) + 1e-5f);
        const float* gp = &g_gate[((size_t)bi * 256 + j0g + j) * 128];
#pragma unroll 8
        for (int h = h0; h < h0 + 64; ++h) {
            float f = __bfloat162float(T[h * 136 + j]);
            float v = ((f - mu) * rs * onw[h] + onb[h]) * gp[h];
            bf16 hi = __float2bfloat16(v);
            Ahi[j * 136 + h] = hi;
            Alo[j * 136 + h] = __float2bfloat16(v - __bfloat162float(hi));
        }
    }
    __syncthreads();
    const int wm = wid & 3, wn = wid >> 2;
    float acc[2][8][4];
    ZERO_ACC(acc);
    gemm3(cvta_s(Ahi), cvta_s(Alo), cvta_s(Whi), cvta_s(Wlo), lane, wm * 32, wn * 64, acc);
    float* Ob = out + ((size_t)bi * 256 + j0g) * 128;
#pragma unroll
    for (int fm = 0; fm < 2; ++fm)
#pragma unroll
        for (int fn = 0; fn < 8; ++fn)
#pragma unroll
            for (int cp = 0; cp < 2; ++cp) {
                int row = wm * 32 + fm * 16 + (lane >> 2) + cp * 8;
                int col = wn * 64 + fn * 8 + ((lane & 3) << 1);
                *(float2*)&Ob[(size_t)row * 128 + col] =
                    make_float2(acc[fm][fn][2 * cp], acc[fm][fn][2 * cp + 1]);
            }
}

extern "C" void kernel_launch(void* const* d_in, const int* in_sizes, int n_in,
                              void* d_out, int out_size) {
    const float* x    = (const float*)d_in[0];
    const float* mask = (const float*)d_in[1];
    const float* nw   = (const float*)d_in[2];
    const float* nb   = (const float*)d_in[3];
    const float* wl   = (const float*)d_in[4];
    const float* wr   = (const float*)d_in[5];
    const float* wlg  = (const float*)d_in[6];
    const float* wrg  = (const float*)d_in[7];
    const float* wog  = (const float*)d_in[8];
    const float* onw  = (const float*)d_in[9];
    const float* onb  = (const float*)d_in[10];
    const float* wout = (const float*)d_in[11];
    float* out = (float*)d_out;

    static bool attr_done = false;
    if (!attr_done) {
        cudaFuncSetAttribute(k1_proj, cudaFuncAttributeMaxDynamicSharedMemorySize, K1_SMEM);
        cudaFuncSetAttribute(k3_out, cudaFuncAttributeMaxDynamicSharedMemorySize, K3_SMEM);
        attr_done = true;
    }
    k0_prep<<<6, 256>>>(wl, wr, wlg, wrg, wog, wout);
    k1_proj<<<dim3(2, 512), 256, K1_SMEM>>>(x, mask, nw, nb);
    k2_tri<<<dim3(4, 256), 256, K2_SMEM>>>();
    k3_out<<<dim3(2, 512), 256, K3_SMEM>>>(onw, onb, out);
}

// round 10
// speedup vs baseline: 1.1951x; 1.1951x over previous
#include <cuda_runtime.h>
#include <cuda_bf16.h>
#include <cstdint>
#include <math.h>

using bf16 = __nv_bfloat16;
#define BB 2
#define SSZ 256

// scratch (device globals; no cudaMalloc allowed)
__device__ bf16  g_left [(size_t)BB * 128 * SSZ * SSZ];  // [b][h][i][k]
__device__ bf16  g_right[(size_t)BB * 128 * SSZ * SSZ];  // [b][h][j][k]
__device__ bf16  g_tri  [(size_t)BB * 128 * SSZ * SSZ];  // [b][h][i][j]
__device__ float g_gate [(size_t)BB * SSZ * SSZ * 128];  // [b][i][h][j]
__device__ bf16  g_whi[6 * 16384];  // 0:left 1:right 2:lg 3:rg 4:og 5:w_out
__device__ bf16  g_wlo[6 * 16384];

static __device__ __forceinline__ uint32_t cvta_s(const void* p) {
    return (uint32_t)__cvta_generic_to_shared(p);
}
static __device__ __forceinline__ void ldsm4(uint32_t a, uint32_t& r0, uint32_t& r1,
                                             uint32_t& r2, uint32_t& r3) {
    asm volatile("ldmatrix.sync.aligned.m8n8.x4.shared.b16 {%0,%1,%2,%3},[%4];"
                 : "=r"(r0), "=r"(r1), "=r"(r2), "=r"(r3) : "r"(a));
}
static __device__ __forceinline__ void ldsm4t(uint32_t a, uint32_t& r0, uint32_t& r1,
                                              uint32_t& r2, uint32_t& r3) {
    asm volatile("ldmatrix.sync.aligned.m8n8.x4.trans.shared.b16 {%0,%1,%2,%3},[%4];"
                 : "=r"(r0), "=r"(r1), "=r"(r2), "=r"(r3) : "r"(a));
}
static __device__ __forceinline__ void mma16816(float* c, const uint32_t* a,
                                                const uint32_t* b) {
    asm volatile(
        "mma.sync.aligned.m16n8k16.row.col.f32.bf16.bf16.f32 "
        "{%0,%1,%2,%3},{%4,%5,%6,%7},{%8,%9},{%0,%1,%2,%3};"
        : "+f"(c[0]), "+f"(c[1]), "+f"(c[2]), "+f"(c[3])
        : "r"(a[0]), "r"(a[1]), "r"(a[2]), "r"(a[3]), "r"(b[0]), "r"(b[1]));
}
template <int SB>  // A operand from [m][k] rows
static __device__ __forceinline__ void load_a(uint32_t base, int m0, int k0, int lane,
                                              uint32_t a[2][4]) {
#pragma unroll
    for (int fm = 0; fm < 2; ++fm) {
        int row = m0 + fm * 16 + (lane & 15), col = k0 + ((lane >> 4) << 3);
        ldsm4(base + row * SB + col * 2, a[fm][0], a[fm][1], a[fm][2], a[fm][3]);
    }
}
template <int SB>  // A operand from transposed storage [k][m] rows (ldmatrix.trans)
static __device__ __forceinline__ void load_at(uint32_t base, int m0, int k0, int lane,
                                               uint32_t a[2][4]) {
#pragma unroll
    for (int fm = 0; fm < 2; ++fm) {
        int row = k0 + (lane & 7) + ((lane >> 4) << 3);
        int col = m0 + fm * 16 + (lane & 8);
        ldsm4t(base + row * SB + col * 2, a[fm][0], a[fm][1], a[fm][2], a[fm][3]);
    }
}
template <int SB>  // 4 m16 frags (64 rows)
static __device__ __forceinline__ void load_a4(uint32_t base, int m0, int k0, int lane,
                                               uint32_t a[4][4]) {
#pragma unroll
    for (int fm = 0; fm < 4; ++fm) {
        int row = m0 + fm * 16 + (lane & 15), col = k0 + ((lane >> 4) << 3);
        ldsm4(base + row * SB + col * 2, a[fm][0], a[fm][1], a[fm][2], a[fm][3]);
    }
}
template <int SB>  // B operand, 64 n-rows as 8 frags
static __device__ __forceinline__ void load_b(uint32_t base, int n0, int k0, int lane,
                                              uint32_t b[8][2]) {
#pragma unroll
    for (int q = 0; q < 4; ++q) {
        int row = n0 + q * 16 + (lane & 7) + ((lane >> 4) << 3);
        int col = k0 + (((lane >> 3) & 1) << 3);
        ldsm4(base + row * SB + col * 2, b[2 * q][0], b[2 * q][1],
              b[2 * q + 1][0], b[2 * q + 1][1]);
    }
}
// plain single-A gemm, K=128, stride 272B
static __device__ __forceinline__ void gemm128(uint32_t sA, uint32_t sB, int lane,
                                               int m0, int n0, float acc[2][8][4]) {
#pragma unroll
    for (int ks = 0; ks < 8; ++ks) {
        uint32_t a[2][4], b[8][2];
        load_a<272>(sA, m0, ks * 16, lane, a);
        load_b<272>(sB, n0, ks * 16, lane, b);
#pragma unroll
        for (int fm = 0; fm < 2; ++fm)
#pragma unroll
            for (int fn = 0; fn < 8; ++fn) mma16816(acc[fm][fn], a[fm], b[fn]);
    }
}
// dual-A gemm (B frags reused): acc += A0*B^T + A1*B^T
static __device__ __forceinline__ void gemm128_dualA(uint32_t sA0, uint32_t sA1,
                                                     uint32_t sB, int lane, int m0,
                                                     int n0, float acc[2][8][4]) {
#pragma unroll
    for (int ks = 0; ks < 8; ++ks) {
        uint32_t a[2][4], b[8][2];
        load_b<272>(sB, n0, ks * 16, lane, b);
        load_a<272>(sA0, m0, ks * 16, lane, a);
#pragma unroll
        for (int fm = 0; fm < 2; ++fm)
#pragma unroll
            for (int fn = 0; fn < 8; ++fn) mma16816(acc[fm][fn], a[fm], b[fn]);
        load_a<272>(sA1, m0, ks * 16, lane, a);
#pragma unroll
        for (int fm = 0; fm < 2; ++fm)
#pragma unroll
            for (int fn = 0; fn < 8; ++fn) mma16816(acc[fm][fn], a[fm], b[fn]);
    }
}
// trans-A gemm with dual B (A frags reused): acc += A*B0^T + A*B1^T
static __device__ __forceinline__ void gemm128_tA_dualB(uint32_t sA, uint32_t sB0,
                                                        uint32_t sB1, int lane, int m0,
                                                        int n0, float acc[2][8][4]) {
#pragma unroll
    for (int ks = 0; ks < 8; ++ks) {
        uint32_t a[2][4], b[8][2];
        load_at<272>(sA, m0, ks * 16, lane, a);
        load_b<272>(sB0, n0, ks * 16, lane, b);
#pragma unroll
        for (int fm = 0; fm < 2; ++fm)
#pragma unroll
            for (int fn = 0; fn < 8; ++fn) mma16816(acc[fm][fn], a[fm], b[fn]);
        load_b<272>(sB1, n0, ks * 16, lane, b);
#pragma unroll
        for (int fm = 0; fm < 2; ++fm)
#pragma unroll
            for (int fn = 0; fn < 8; ++fn) mma16816(acc[fm][fn], a[fm], b[fn]);
    }
}
static __device__ __forceinline__ void gemm128_tA(uint32_t sA, uint32_t sB, int lane,
                                                  int m0, int n0, float acc[2][8][4]) {
#pragma unroll
    for (int ks = 0; ks < 8; ++ks) {
        uint32_t a[2][4], b[8][2];
        load_at<272>(sA, m0, ks * 16, lane, a);
        load_b<272>(sB, n0, ks * 16, lane, b);
#pragma unroll
        for (int fm = 0; fm < 2; ++fm)
#pragma unroll
            for (int fn = 0; fn < 8; ++fn) mma16816(acc[fm][fn], a[fm], b[fn]);
    }
}
static __device__ __forceinline__ float warpsum(float v) {
#pragma unroll
    for (int o = 16; o > 0; o >>= 1) v += __shfl_xor_sync(0xffffffffu, v, o);
    return v;
}
static __device__ __forceinline__ float sigmoidf_(float g) {
    return 1.0f / (1.0f + __expf(-g));
}
#define ZERO_ACC(acc)                                           \
    {                                                           \
        _Pragma("unroll") for (int z1 = 0; z1 < 2; ++z1)        \
            _Pragma("unroll") for (int z2 = 0; z2 < 8; ++z2)    \
                _Pragma("unroll") for (int z3 = 0; z3 < 4; ++z3)\
                    acc[z1][z2][z3] = 0.f;                      \
    }

// ---------------- K0: split weights ----------------
__global__ void k0_prep(const float* wl, const float* wr, const float* wlg,
                        const float* wrg, const float* wog, const float* wout) {
    const float* srcs[6] = {wl, wr, wlg, wrg, wog, wout};
    const float* s = srcs[blockIdx.x];
    int base = blockIdx.x * 16384;
    for (int i = threadIdx.x; i < 16384; i += 256) {
        float v = s[i];
        bf16 h = __float2bfloat16(v);
        g_whi[base + i] = h;
        g_wlo[base + i] = __float2bfloat16(v - __bfloat162float(h));
    }
}

// ---------------- K1: LN + 5 projections + gating (swapped operands, 3-term) -------
// grid (2 kt, 512 bi), 256 thr. acc = [out_ch rows][k cols] -> direct stores.
// 3-term split: (Whi+Wlo)*Xhi + Whi*Xlo for projections AND gates.
#define K1_SMEM (6 * 34816 + 512)
__global__ void __launch_bounds__(256, 1)
k1_proj(const float* __restrict__ x, const float* __restrict__ mask,
        const float* __restrict__ nw, const float* __restrict__ nb) {
    extern __shared__ char sm[];
    bf16* Ahi = (bf16*)sm;           // Xn_hi [k=128][d=128] stride 136
    bf16* Alo = Ahi + 128 * 136;     // Xn_lo
    bf16* W0 = Alo + 128 * 136;      // proj Whi
    bf16* W1 = W0 + 128 * 136;       // proj Wlo
    bf16* W2 = W1 + 128 * 136;       // gate Whi
    bf16* W3 = W2 + 128 * 136;       // gate Wlo
    float* msk = (float*)(sm + 6 * 34816);
    const int tid = threadIdx.x, lane = tid & 31, wid = tid >> 5;
    const int kt = blockIdx.x, bi = blockIdx.y;
    const int b = bi >> 8, i = bi & 255, k0g = kt * 128;

    if (tid < 128) msk[tid] = mask[(size_t)bi * 256 + k0g + tid];
    const float4 nwv = reinterpret_cast<const float4*>(nw)[lane];
    const float4 nbv = reinterpret_cast<const float4*>(nb)[lane];
    for (int r = wid * 16; r < wid * 16 + 16; ++r) {
        const float4 v = reinterpret_cast<const float4*>(
            x + ((size_t)bi * 256 + k0g + r) * 128)[lane];
        float mu = warpsum(v.x + v.y + v.z + v.w) * 0.0078125f;
        float dx = v.x - mu, dy = v.y - mu, dz = v.z - mu, dw = v.w - mu;
        float rs = rsqrtf(warpsum(dx * dx + dy * dy + dz * dz + dw * dw) * 0.0078125f + 1e-5f);
        float f0 = dx * rs * nwv.x + nbv.x, f1 = dy * rs * nwv.y + nbv.y;
        float f2 = dz * rs * nwv.z + nbv.z, f3 = dw * rs * nwv.w + nbv.w;
        bf16 h0 = __float2bfloat16(f0), h1 = __float2bfloat16(f1);
        bf16 h2 = __float2bfloat16(f2), h3 = __float2bfloat16(f3);
        __nv_bfloat162* ph = (__nv_bfloat162*)(Ahi + r * 136 + lane * 4);
        ph[0] = __nv_bfloat162(h0, h1);
        ph[1] = __nv_bfloat162(h2, h3);
        __nv_bfloat162* pl = (__nv_bfloat162*)(Alo + r * 136 + lane * 4);
        pl[0] = __nv_bfloat162(__float2bfloat16(f0 - __bfloat162float(h0)),
                               __float2bfloat16(f1 - __bfloat162float(h1)));
        pl[1] = __nv_bfloat162(__float2bfloat16(f2 - __bfloat162float(h2)),
                               __float2bfloat16(f3 - __bfloat162float(h3)));
    }
    __syncthreads();
    const uint32_t sAh = cvta_s(Ahi), sAl = cvta_s(Alo);
    const uint32_t sW0 = cvta_s(W0), sW1 = cvta_s(W1);
    const uint32_t sW2 = cvta_s(W2), sW3 = cvta_s(W3);
    const int wm = wid & 3, wn = wid >> 2;  // m: 4x32 out_ch, n: 2x64 k

#pragma unroll 1
    for (int pass = 0; pass < 2; ++pass) {
        const bf16* srcs[4] = {g_whi + pass * 16384, g_wlo + pass * 16384,
                               g_whi + (2 + pass) * 16384, g_wlo + (2 + pass) * 16384};
        bf16* dsts[4] = {W0, W1, W2, W3};
#pragma unroll
        for (int mtx = 0; mtx < 4; ++mtx)
#pragma unroll
            for (int it = 0; it < 8; ++it) {
                int idx = it * 256 + tid, row = idx >> 4, c8 = (idx & 15) << 3;
                *(uint4*)(dsts[mtx] + row * 136 + c8) =
                    *(const uint4*)(srcs[mtx] + row * 128 + c8);
            }
        __syncthreads();
        float accP[2][8][4], accG[2][8][4];
        ZERO_ACC(accP); ZERO_ACC(accG);
        gemm128_dualA(sW0, sW1, sAh, lane, wm * 32, wn * 64, accP);  // (Whi+Wlo)*Xhi
        gemm128(sW0, sAl, lane, wm * 32, wn * 64, accP);             // Whi*Xlo
        gemm128_dualA(sW2, sW3, sAh, lane, wm * 32, wn * 64, accG);
        gemm128(sW2, sAl, lane, wm * 32, wn * 64, accG);
        bf16* dst = pass == 0 ? g_left : g_right;
#pragma unroll
        for (int fm = 0; fm < 2; ++fm)
#pragma unroll
            for (int fn = 0; fn < 8; ++fn)
#pragma unroll
                for (int cp = 0; cp < 2; ++cp) {
                    int row = wm * 32 + fm * 16 + (lane >> 2) + cp * 8;  // out_ch h
                    int col = wn * 64 + fn * 8 + ((lane & 3) << 1);      // k
                    float2 mk = *(float2*)(msk + col);
                    float v0 = accP[fm][fn][2 * cp] * mk.x * sigmoidf_(accG[fm][fn][2 * cp]);
                    float v1 = accP[fm][fn][2 * cp + 1] * mk.y *
                               sigmoidf_(accG[fm][fn][2 * cp + 1]);
                    *(__nv_bfloat162*)&dst[(((size_t)b * 128 + row) * 256 + i) * 256 +
                                           k0g + col] = __floats2bfloat162_rn(v0, v1);
                }
        __syncthreads();
    }
    // out-gate pass (3-term), store fp32 sigmoid -> g_gate[b][i][h][j]
#pragma unroll
    for (int it = 0; it < 8; ++it) {
        int idx = it * 256 + tid, row = idx >> 4, c8 = (idx & 15) << 3;
        *(uint4*)(W0 + row * 136 + c8) = *(const uint4*)(g_whi + 4 * 16384 + row * 128 + c8);
        *(uint4*)(W1 + row * 136 + c8) = *(const uint4*)(g_wlo + 4 * 16384 + row * 128 + c8);
    }
    __syncthreads();
    float accG[2][8][4];
    ZERO_ACC(accG);
    gemm128_dualA(sW0, sW1, sAh, lane, wm * 32, wn * 64, accG);
    gemm128(sW0, sAl, lane, wm * 32, wn * 64, accG);
#pragma unroll
    for (int fm = 0; fm < 2; ++fm)
#pragma unroll
        for (int fn = 0; fn < 8; ++fn)
#pragma unroll
            for (int cp = 0; cp < 2; ++cp) {
                int row = wm * 32 + fm * 16 + (lane >> 2) + cp * 8;  // h
                int col = wn * 64 + fn * 8 + ((lane & 3) << 1);      // j(=k)
                *(float2*)&g_gate[((size_t)bi * 128 + row) * 256 + k0g + col] =
                    make_float2(sigmoidf_(accG[fm][fn][2 * cp]),
                                sigmoidf_(accG[fm][fn][2 * cp + 1]));
            }
}

// ---------------- K2: batched 256^3 bf16 NT GEMM, k fully resident ----------------
// grid (2 ti, 256 p), 256 thr; block out = 128i x 256j; warp tile 64x64
#define K2_SMEM (128 * 264 * 2 + 256 * 264 * 2)
__global__ void __launch_bounds__(256, 1) k2_tri() {
    extern __shared__ char sm[];
    bf16* As = (bf16*)sm;            // [128][264]
    bf16* Bs = As + 128 * 264;       // [256][264]
    const int tid = threadIdx.x, lane = tid & 31, wid = tid >> 5;
    const int wm = wid & 1, wn = wid >> 1;  // 2x64 m, 4x64 n
    const int p = blockIdx.y, ti = blockIdx.x;
    const uint4* Lg = (const uint4*)(g_left + (size_t)p * 65536 + (size_t)ti * 32768);
    const uint4* Rg = (const uint4*)(g_right + (size_t)p * 65536);
#pragma unroll
    for (int it = 0; it < 16; ++it) {
        int idx = it * 256 + tid, r = idx >> 5, c8 = (idx & 31) << 3;
        *(uint4*)(As + r * 264 + c8) = Lg[idx];
    }
#pragma unroll
    for (int it = 0; it < 32; ++it) {
        int idx = it * 256 + tid, r = idx >> 5, c8 = (idx & 31) << 3;
        *(uint4*)(Bs + r * 264 + c8) = Rg[idx];
    }
    __syncthreads();
    const uint32_t sA = cvta_s(As), sB = cvta_s(Bs);
    float acc[4][8][4];
#pragma unroll
    for (int z1 = 0; z1 < 4; ++z1)
#pragma unroll
        for (int z2 = 0; z2 < 8; ++z2)
#pragma unroll
            for (int z3 = 0; z3 < 4; ++z3) acc[z1][z2][z3] = 0.f;
#pragma unroll 1
    for (int ks = 0; ks < 16; ++ks) {
        uint32_t a[4][4], b[8][2];
        load_a4<528>(sA, wm * 64, ks * 16, lane, a);
        load_b<528>(sB, wn * 64, ks * 16, lane, b);
#pragma unroll
        for (int fm = 0; fm < 4; ++fm)
#pragma unroll
            for (int fn = 0; fn < 8; ++fn) mma16816(acc[fm][fn], a[fm], b[fn]);
    }
    bf16* Og = g_tri + (size_t)p * 65536 + (size_t)ti * 32768;
#pragma unroll
    for (int fm = 0; fm < 4; ++fm)
#pragma unroll
        for (int fn = 0; fn < 8; ++fn)
#pragma unroll
            for (int cp = 0; cp < 2; ++cp) {
                int row = wm * 64 + fm * 16 + (lane >> 2) + cp * 8;
                int col = wn * 64 + fn * 8 + ((lane & 3) << 1);
                *(__nv_bfloat162*)&Og[(size_t)row * 256 + col] =
                    __floats2bfloat162_rn(acc[fm][fn][2 * cp], acc[fm][fn][2 * cp + 1]);
            }
}

// ---------------- K3: LN over h + gate + 3-term output GEMM ----------------
// grid (2 jt, 512 bi), 256 thr. V stored [h][j]; A via ldmatrix.trans.
#define K3_SMEM (4 * 34816 + 2 * 4224 + 1024)
__global__ void __launch_bounds__(256, 1)
k3_out(const float* __restrict__ onw, const float* __restrict__ onb,
       float* __restrict__ out) {
    extern __shared__ char sm[];
    bf16* Vhi = (bf16*)sm;             // [h=128][j=128] stride 136 (raw tri, then hi)
    bf16* Vlo = Vhi + 128 * 136;
    bf16* Whi = Vlo + 128 * 136;       // w_out [dim][hid] stride 136
    bf16* Wlo = Whi + 128 * 136;
    float* red1 = (float*)(sm + 4 * 34816);          // [8][132]
    float* red2 = red1 + 8 * 132;
    float* smu = red2 + 8 * 132;                      // [128]
    float* srs = smu + 128;
    const int tid = threadIdx.x, lane = tid & 31, wid = tid >> 5;
    const int jt = blockIdx.x, bi = blockIdx.y;
    const int b = bi >> 8, i = bi & 255, j0g = jt * 128;

#pragma unroll
    for (int it = 0; it < 8; ++it) {
        int idx = it * 256 + tid, h = idx >> 4, c8 = (idx & 15) << 3;
        *(uint4*)(Vhi + h * 136 + c8) =
            *(const uint4*)&g_tri[(((size_t)b * 128 + h) * 256 + i) * 256 + j0g + c8];
        *(uint4*)(Whi + h * 136 + c8) = *(const uint4*)(g_whi + 5 * 16384 + h * 128 + c8);
        *(uint4*)(Wlo + h * 136 + c8) = *(const uint4*)(g_wlo + 5 * 16384 + h * 128 + c8);
    }
    __syncthreads();
    // LN stats over h: warp-partial sums, conflict-free row reads
    {
        float s1[4] = {0.f, 0.f, 0.f, 0.f}, s2[4] = {0.f, 0.f, 0.f, 0.f};
#pragma unroll
        for (int r = 0; r < 16; ++r) {
            int h = wid * 16 + r;
            uint2 raw = *(const uint2*)(Vhi + h * 136 + 4 * lane);
            float2 p0 = __bfloat1622float2(*(__nv_bfloat162*)&raw.x);
            float2 p1 = __bfloat1622float2(*(__nv_bfloat162*)&raw.y);
            s1[0] += p0.x; s2[0] += p0.x * p0.x;
            s1[1] += p0.y; s2[1] += p0.y * p0.y;
            s1[2] += p1.x; s2[2] += p1.x * p1.x;
            s1[3] += p1.y; s2[3] += p1.y * p1.y;
        }
        *(float4*)(red1 + wid * 132 + 4 * lane) = make_float4(s1[0], s1[1], s1[2], s1[3]);
        *(float4*)(red2 + wid * 132 + 4 * lane) = make_float4(s2[0], s2[1], s2[2], s2[3]);
    }
    __syncthreads();
    if (tid < 128) {
        float a = 0.f, c = 0.f;
#pragma unroll
        for (int w = 0; w < 8; ++w) { a += red1[w * 132 + tid]; c += red2[w * 132 + tid]; }
        float mu = a * 0.0078125f;
        float var = c * 0.0078125f - mu * mu;
        smu[tid] = mu;
        srs[tid] = rsqrtf(fmaxf(var, 0.f) + 1e-5f);
    }
    __syncthreads();
    // normalize + gate, in place, hi/lo split; gate read coalesced from global
    {
        const float4 mu4 = *(const float4*)(smu + 4 * lane);
        const float4 rs4 = *(const float4*)(srs + 4 * lane);
#pragma unroll
        for (int r = 0; r < 16; ++r) {
            int h = wid * 16 + r;
            float wn_ = __ldg(onw + h), bb_ = __ldg(onb + h);
            float4 g4 = *(const float4*)&g_gate[((size_t)bi * 128 + h) * 256 + j0g + 4 * lane];
            uint2 raw = *(const uint2*)(Vhi + h * 136 + 4 * lane);
            float2 p0 = __bfloat1622float2(*(__nv_bfloat162*)&raw.x);
            float2 p1 = __bfloat1622float2(*(__nv_bfloat162*)&raw.y);
            float v0 = ((p0.x - mu4.x) * rs4.x * wn_ + bb_) * g4.x;
            float v1 = ((p0.y - mu4.y) * rs4.y * wn_ + bb_) * g4.y;
            float v2 = ((p1.x - mu4.z) * rs4.z * wn_ + bb_) * g4.z;
            float v3 = ((p1.y - mu4.w) * rs4.w * wn_ + bb_) * g4.w;
            __nv_bfloat162 h0 = __floats2bfloat162_rn(v0, v1);
            __nv_bfloat162 h1 = __floats2bfloat162_rn(v2, v3);
            float2 q0 = __bfloat1622float2(h0), q1 = __bfloat1622float2(h1);
            uint2 hp, lp;
            *(__nv_bfloat162*)&hp.x = h0;
            *(__nv_bfloat162*)&hp.y = h1;
            *(__nv_bfloat162*)&lp.x = __floats2bfloat162_rn(v0 - q0.x, v1 - q0.y);
            *(__nv_bfloat162*)&lp.y = __floats2bfloat162_rn(v2 - q1.x, v3 - q1.y);
            *(uint2*)(Vhi + h * 136 + 4 * lane) = hp;
            *(uint2*)(Vlo + h * 136 + 4 * lane) = lp;
        }
    }
    __syncthreads();
    // GEMM: out[j][dim] = V * Wout^T, 3-term split; A via ldmatrix.trans from [h][j]
    const int wm = wid & 3, wn = wid >> 2;  // m: 4x32 j, n: 2x64 dim
    float acc[2][8][4];
    ZERO_ACC(acc);
    gemm128_tA_dualB(cvta_s(Vhi), cvta_s(Whi), cvta_s(Wlo), lane, wm * 32, wn * 64, acc);
    gemm128_tA(cvta_s(Vlo), cvta_s(Whi), lane, wm * 32, wn * 64, acc);
    float* Ob = out + ((size_t)bi * 256 + j0g) * 128;
#pragma unroll
    for (int fm = 0; fm < 2; ++fm)
#pragma unroll
        for (int fn = 0; fn < 8; ++fn)
#pragma unroll
            for (int cp = 0; cp < 2; ++cp) {
                int row = wm * 32 + fm * 16 + (lane >> 2) + cp * 8;  // j
                int col = wn * 64 + fn * 8 + ((lane & 3) << 1);      // dim
                *(float2*)&Ob[(size_t)row * 128 + col] =
                    make_float2(acc[fm][fn][2 * cp], acc[fm][fn][2 * cp + 1]);
            }
}

extern "C" void kernel_launch(void* const* d_in, const int* in_sizes, int n_in,
                              void* d_out, int out_size) {
    const float* x    = (const float*)d_in[0];
    const float* mask = (const float*)d_in[1];
    const float* nw   = (const float*)d_in[2];
    const float* nb   = (const float*)d_in[3];
    const float* wl   = (const float*)d_in[4];
    const float* wr   = (const float*)d_in[5];
    const float* wlg  = (const float*)d_in[6];
    const float* wrg  = (const float*)d_in[7];
    const float* wog  = (const float*)d_in[8];
    const float* onw  = (const float*)d_in[9];
    const float* onb  = (const float*)d_in[10];
    const float* wout = (const float*)d_in[11];
    float* out = (float*)d_out;

    static bool attr_done = false;
    if (!attr_done) {
        cudaFuncSetAttribute(k1_proj, cudaFuncAttributeMaxDynamicSharedMemorySize, K1_SMEM);
        cudaFuncSetAttribute(k2_tri, cudaFuncAttributeMaxDynamicSharedMemorySize, K2_SMEM);
        cudaFuncSetAttribute(k3_out, cudaFuncAttributeMaxDynamicSharedMemorySize, K3_SMEM);
        attr_done = true;
    }
    k0_prep<<<6, 256>>>(wl, wr, wlg, wrg, wog, wout);
    k1_proj<<<dim3(2, 512), 256, K1_SMEM>>>(x, mask, nw, nb);
    k2_tri<<<dim3(2, 256), 256, K2_SMEM>>>();
    k3_out<<<dim3(2, 512), 256, K3_SMEM>>>(onw, onb, out);
}

// round 11
// speedup vs baseline: 1.7412x; 1.4570x over previous
#include <cuda_runtime.h>
#include <cuda_bf16.h>
#include <cstdint>
#include <math.h>

using bf16 = __nv_bfloat16;
#define BB 2
#define SSZ 256

// scratch (device globals; no cudaMalloc allowed)
__device__ bf16  g_left [(size_t)BB * 128 * SSZ * SSZ];  // [b][h][i][k]
__device__ bf16  g_right[(size_t)BB * 128 * SSZ * SSZ];  // [b][h][j][k]
__device__ bf16  g_tri  [(size_t)BB * 128 * SSZ * SSZ];  // [b][h][i][j]
__device__ float g_gate [(size_t)BB * SSZ * SSZ * 128];  // [b][i][h][j]
__device__ bf16  g_whi[6 * 16384];  // 0:left 1:right 2:lg 3:rg 4:og 5:w_out
__device__ bf16  g_wlo[6 * 16384];

static __device__ __forceinline__ uint32_t cvta_s(const void* p) {
    return (uint32_t)__cvta_generic_to_shared(p);
}
static __device__ __forceinline__ void ldsm4(uint32_t a, uint32_t& r0, uint32_t& r1,
                                             uint32_t& r2, uint32_t& r3) {
    asm volatile("ldmatrix.sync.aligned.m8n8.x4.shared.b16 {%0,%1,%2,%3},[%4];"
                 : "=r"(r0), "=r"(r1), "=r"(r2), "=r"(r3) : "r"(a));
}
static __device__ __forceinline__ void ldsm4t(uint32_t a, uint32_t& r0, uint32_t& r1,
                                              uint32_t& r2, uint32_t& r3) {
    asm volatile("ldmatrix.sync.aligned.m8n8.x4.trans.shared.b16 {%0,%1,%2,%3},[%4];"
                 : "=r"(r0), "=r"(r1), "=r"(r2), "=r"(r3) : "r"(a));
}
static __device__ __forceinline__ void mma16816(float* c, const uint32_t* a,
                                                const uint32_t* b) {
    asm volatile(
        "mma.sync.aligned.m16n8k16.row.col.f32.bf16.bf16.f32 "
        "{%0,%1,%2,%3},{%4,%5,%6,%7},{%8,%9},{%0,%1,%2,%3};"
        : "+f"(c[0]), "+f"(c[1]), "+f"(c[2]), "+f"(c[3])
        : "r"(a[0]), "r"(a[1]), "r"(a[2]), "r"(a[3]), "r"(b[0]), "r"(b[1]));
}
template <int SB>  // A operand from [m][k] rows, 32 m-rows (2 frags)
static __device__ __forceinline__ void load_a(uint32_t base, int m0, int k0, int lane,
                                              uint32_t a[2][4]) {
#pragma unroll
    for (int fm = 0; fm < 2; ++fm) {
        int row = m0 + fm * 16 + (lane & 15), col = k0 + ((lane >> 4) << 3);
        ldsm4(base + row * SB + col * 2, a[fm][0], a[fm][1], a[fm][2], a[fm][3]);
    }
}
template <int SB>  // A from transposed storage [k][m], 32 m-cols (ldmatrix.trans)
static __device__ __forceinline__ void load_at(uint32_t base, int m0, int k0, int lane,
                                               uint32_t a[2][4]) {
#pragma unroll
    for (int fm = 0; fm < 2; ++fm) {
        int row = k0 + (lane & 7) + ((lane >> 4) << 3);
        int col = m0 + fm * 16 + (lane & 8);
        ldsm4t(base + row * SB + col * 2, a[fm][0], a[fm][1], a[fm][2], a[fm][3]);
    }
}
template <int SB>  // 4 m16 frags (64 rows)
static __device__ __forceinline__ void load_a4(uint32_t base, int m0, int k0, int lane,
                                               uint32_t a[4][4]) {
#pragma unroll
    for (int fm = 0; fm < 4; ++fm) {
        int row = m0 + fm * 16 + (lane & 15), col = k0 + ((lane >> 4) << 3);
        ldsm4(base + row * SB + col * 2, a[fm][0], a[fm][1], a[fm][2], a[fm][3]);
    }
}
template <int SB>  // B operand, 64 n-rows (8 frags)
static __device__ __forceinline__ void load_b(uint32_t base, int n0, int k0, int lane,
                                              uint32_t b[8][2]) {
#pragma unroll
    for (int q = 0; q < 4; ++q) {
        int row = n0 + q * 16 + (lane & 7) + ((lane >> 4) << 3);
        int col = k0 + (((lane >> 3) & 1) << 3);
        ldsm4(base + row * SB + col * 2, b[2 * q][0], b[2 * q][1],
              b[2 * q + 1][0], b[2 * q + 1][1]);
    }
}
template <int SB>  // B operand, 32 n-rows (4 frags)
static __device__ __forceinline__ void load_b32(uint32_t base, int n0, int k0, int lane,
                                                uint32_t b[4][2]) {
#pragma unroll
    for (int q = 0; q < 2; ++q) {
        int row = n0 + q * 16 + (lane & 7) + ((lane >> 4) << 3);
        int col = k0 + (((lane >> 3) & 1) << 3);
        ldsm4(base + row * SB + col * 2, b[2 * q][0], b[2 * q][1],
              b[2 * q + 1][0], b[2 * q + 1][1]);
    }
}
static __device__ __forceinline__ void mma8(float acc[2][4][4], const uint32_t a[2][4],
                                            const uint32_t b[4][2]) {
#pragma unroll
    for (int fm = 0; fm < 2; ++fm)
#pragma unroll
        for (int fn = 0; fn < 4; ++fn) mma16816(acc[fm][fn], a[fm], b[fn]);
}
static __device__ __forceinline__ float warpsum(float v) {
#pragma unroll
    for (int o = 16; o > 0; o >>= 1) v += __shfl_xor_sync(0xffffffffu, v, o);
    return v;
}
static __device__ __forceinline__ float sigmoidf_(float g) {
    return 1.0f / (1.0f + __expf(-g));
}
#define ZERO_ACC44(acc)                                         \
    {                                                           \
        _Pragma("unroll") for (int z1 = 0; z1 < 2; ++z1)        \
            _Pragma("unroll") for (int z2 = 0; z2 < 4; ++z2)    \
                _Pragma("unroll") for (int z3 = 0; z3 < 4; ++z3)\
                    acc[z1][z2][z3] = 0.f;                      \
    }

// ---------------- K0: split weights ----------------
__global__ void k0_prep(const float* wl, const float* wr, const float* wlg,
                        const float* wrg, const float* wog, const float* wout) {
    const float* srcs[6] = {wl, wr, wlg, wrg, wog, wout};
    const float* s = srcs[blockIdx.x];
    int base = blockIdx.x * 16384;
    for (int i = threadIdx.x; i < 16384; i += 256) {
        float v = s[i];
        bf16 h = __float2bfloat16(v);
        g_whi[base + i] = h;
        g_wlo[base + i] = __float2bfloat16(v - __bfloat162float(h));
    }
}

// ---------------- K1: LN + 5 projections + gating (512 thr, fused dual-acc) -------
// grid (2 kt, 512 bi). Warp tile 32x32, 4m x 4n. 3-term: (Whi+Wlo)*Xhi + Whi*Xlo.
#define K1_SMEM (6 * 34816 + 512)
__global__ void __launch_bounds__(512, 1)
k1_proj(const float* __restrict__ x, const float* __restrict__ mask,
        const float* __restrict__ nw, const float* __restrict__ nb) {
    extern __shared__ char sm[];
    bf16* Ahi = (bf16*)sm;           // Xn_hi [k=128][d=128] stride 136
    bf16* Alo = Ahi + 128 * 136;     // Xn_lo
    bf16* W0 = Alo + 128 * 136;      // proj Whi
    bf16* W1 = W0 + 128 * 136;       // proj Wlo
    bf16* W2 = W1 + 128 * 136;       // gate Whi
    bf16* W3 = W2 + 128 * 136;       // gate Wlo
    float* msk = (float*)(sm + 6 * 34816);
    const int tid = threadIdx.x, lane = tid & 31, wid = tid >> 5;
    const int kt = blockIdx.x, bi = blockIdx.y;
    const int b = bi >> 8, i = bi & 255, k0g = kt * 128;

    if (tid < 128) msk[tid] = mask[(size_t)bi * 256 + k0g + tid];
    const float4 nwv = reinterpret_cast<const float4*>(nw)[lane];
    const float4 nbv = reinterpret_cast<const float4*>(nb)[lane];
    for (int r = wid * 8; r < wid * 8 + 8; ++r) {
        const float4 v = reinterpret_cast<const float4*>(
            x + ((size_t)bi * 256 + k0g + r) * 128)[lane];
        float mu = warpsum(v.x + v.y + v.z + v.w) * 0.0078125f;
        float dx = v.x - mu, dy = v.y - mu, dz = v.z - mu, dw = v.w - mu;
        float rs = rsqrtf(warpsum(dx * dx + dy * dy + dz * dz + dw * dw) * 0.0078125f + 1e-5f);
        float f0 = dx * rs * nwv.x + nbv.x, f1 = dy * rs * nwv.y + nbv.y;
        float f2 = dz * rs * nwv.z + nbv.z, f3 = dw * rs * nwv.w + nbv.w;
        bf16 h0 = __float2bfloat16(f0), h1 = __float2bfloat16(f1);
        bf16 h2 = __float2bfloat16(f2), h3 = __float2bfloat16(f3);
        __nv_bfloat162* ph = (__nv_bfloat162*)(Ahi + r * 136 + lane * 4);
        ph[0] = __nv_bfloat162(h0, h1);
        ph[1] = __nv_bfloat162(h2, h3);
        __nv_bfloat162* pl = (__nv_bfloat162*)(Alo + r * 136 + lane * 4);
        pl[0] = __nv_bfloat162(__float2bfloat16(f0 - __bfloat162float(h0)),
                               __float2bfloat16(f1 - __bfloat162float(h1)));
        pl[1] = __nv_bfloat162(__float2bfloat16(f2 - __bfloat162float(h2)),
                               __float2bfloat16(f3 - __bfloat162float(h3)));
    }
    __syncthreads();
    const uint32_t sAh = cvta_s(Ahi), sAl = cvta_s(Alo);
    const uint32_t sW0 = cvta_s(W0), sW1 = cvta_s(W1);
    const uint32_t sW2 = cvta_s(W2), sW3 = cvta_s(W3);
    const int wm = wid & 3, wn = wid >> 2;  // m: 4x32 out_ch, n: 4x32 k
    const int m0 = wm * 32, n0 = wn * 32;

#pragma unroll 1
    for (int pass = 0; pass < 2; ++pass) {
        const bf16* srcs[4] = {g_whi + pass * 16384, g_wlo + pass * 16384,
                               g_whi + (2 + pass) * 16384, g_wlo + (2 + pass) * 16384};
        bf16* dsts[4] = {W0, W1, W2, W3};
#pragma unroll
        for (int mtx = 0; mtx < 4; ++mtx)
#pragma unroll
            for (int it = 0; it < 4; ++it) {
                int idx = it * 512 + tid, row = idx >> 4, c8 = (idx & 15) << 3;
                *(uint4*)(dsts[mtx] + row * 136 + c8) =
                    *(const uint4*)(srcs[mtx] + row * 128 + c8);
            }
        __syncthreads();
        float accP[2][4][4], accG[2][4][4];
        ZERO_ACC44(accP); ZERO_ACC44(accG);
#pragma unroll
        for (int ks = 0; ks < 8; ++ks) {  // B(Xhi) loaded once, 4 A matrices
            uint32_t bfr[4][2], aP[2][4], aG[2][4];
            load_b32<272>(sAh, n0, ks * 16, lane, bfr);
            load_a<272>(sW0, m0, ks * 16, lane, aP);
            load_a<272>(sW2, m0, ks * 16, lane, aG);
            mma8(accP, aP, bfr);
            mma8(accG, aG, bfr);
            load_a<272>(sW1, m0, ks * 16, lane, aP);
            load_a<272>(sW3, m0, ks * 16, lane, aG);
            mma8(accP, aP, bfr);
            mma8(accG, aG, bfr);
        }
#pragma unroll
        for (int ks = 0; ks < 8; ++ks) {  // B(Xlo), hi-weights only
            uint32_t bfr[4][2], aP[2][4], aG[2][4];
            load_b32<272>(sAl, n0, ks * 16, lane, bfr);
            load_a<272>(sW0, m0, ks * 16, lane, aP);
            load_a<272>(sW2, m0, ks * 16, lane, aG);
            mma8(accP, aP, bfr);
            mma8(accG, aG, bfr);
        }
        bf16* dst = pass == 0 ? g_left : g_right;
#pragma unroll
        for (int fm = 0; fm < 2; ++fm)
#pragma unroll
            for (int fn = 0; fn < 4; ++fn)
#pragma unroll
                for (int cp = 0; cp < 2; ++cp) {
                    int row = m0 + fm * 16 + (lane >> 2) + cp * 8;  // out_ch h
                    int col = n0 + fn * 8 + ((lane & 3) << 1);      // k
                    float2 mk = *(float2*)(msk + col);
                    float v0 = accP[fm][fn][2 * cp] * mk.x * sigmoidf_(accG[fm][fn][2 * cp]);
                    float v1 = accP[fm][fn][2 * cp + 1] * mk.y *
                               sigmoidf_(accG[fm][fn][2 * cp + 1]);
                    *(__nv_bfloat162*)&dst[(((size_t)b * 128 + row) * 256 + i) * 256 +
                                           k0g + col] = __floats2bfloat162_rn(v0, v1);
                }
        __syncthreads();
    }
    // out-gate pass (3-term), store fp32 sigmoid -> g_gate[b][i][h][j]
#pragma unroll
    for (int it = 0; it < 4; ++it) {
        int idx = it * 512 + tid, row = idx >> 4, c8 = (idx & 15) << 3;
        *(uint4*)(W0 + row * 136 + c8) = *(const uint4*)(g_whi + 4 * 16384 + row * 128 + c8);
        *(uint4*)(W1 + row * 136 + c8) = *(const uint4*)(g_wlo + 4 * 16384 + row * 128 + c8);
    }
    __syncthreads();
    float accG[2][4][4];
    ZERO_ACC44(accG);
#pragma unroll
    for (int ks = 0; ks < 8; ++ks) {
        uint32_t bfr[4][2], a0[2][4], a1[2][4];
        load_b32<272>(sAh, n0, ks * 16, lane, bfr);
        load_a<272>(sW0, m0, ks * 16, lane, a0);
        load_a<272>(sW1, m0, ks * 16, lane, a1);
        mma8(accG, a0, bfr);
        mma8(accG, a1, bfr);
    }
#pragma unroll
    for (int ks = 0; ks < 8; ++ks) {
        uint32_t bfr[4][2], a0[2][4];
        load_b32<272>(sAl, n0, ks * 16, lane, bfr);
        load_a<272>(sW0, m0, ks * 16, lane, a0);
        mma8(accG, a0, bfr);
    }
#pragma unroll
    for (int fm = 0; fm < 2; ++fm)
#pragma unroll
        for (int fn = 0; fn < 4; ++fn)
#pragma unroll
            for (int cp = 0; cp < 2; ++cp) {
                int row = m0 + fm * 16 + (lane >> 2) + cp * 8;  // h
                int col = n0 + fn * 8 + ((lane & 3) << 1);      // j(=k)
                *(float2*)&g_gate[((size_t)bi * 128 + row) * 256 + k0g + col] =
                    make_float2(sigmoidf_(accG[fm][fn][2 * cp]),
                                sigmoidf_(accG[fm][fn][2 * cp + 1]));
            }
}

// ---------------- K2: batched 256^3 bf16 NT GEMM, k fully resident ----------------
// grid (2 ti, 256 p), 256 thr; block out = 128i x 256j; warp tile 64x64
#define K2_SMEM (128 * 264 * 2 + 256 * 264 * 2)
__global__ void __launch_bounds__(256, 1) k2_tri() {
    extern __shared__ char sm[];
    bf16* As = (bf16*)sm;            // [128][264]
    bf16* Bs = As + 128 * 264;       // [256][264]
    const int tid = threadIdx.x, lane = tid & 31, wid = tid >> 5;
    const int wm = wid & 1, wn = wid >> 1;  // 2x64 m, 4x64 n
    const int p = blockIdx.y, ti = blockIdx.x;
    const uint4* Lg = (const uint4*)(g_left + (size_t)p * 65536 + (size_t)ti * 32768);
    const uint4* Rg = (const uint4*)(g_right + (size_t)p * 65536);
#pragma unroll
    for (int it = 0; it < 16; ++it) {
        int idx = it * 256 + tid, r = idx >> 5, c8 = (idx & 31) << 3;
        *(uint4*)(As + r * 264 + c8) = Lg[idx];
    }
#pragma unroll
    for (int it = 0; it < 32; ++it) {
        int idx = it * 256 + tid, r = idx >> 5, c8 = (idx & 31) << 3;
        *(uint4*)(Bs + r * 264 + c8) = Rg[idx];
    }
    __syncthreads();
    const uint32_t sA = cvta_s(As), sB = cvta_s(Bs);
    float acc[4][8][4];
#pragma unroll
    for (int z1 = 0; z1 < 4; ++z1)
#pragma unroll
        for (int z2 = 0; z2 < 8; ++z2)
#pragma unroll
            for (int z3 = 0; z3 < 4; ++z3) acc[z1][z2][z3] = 0.f;
#pragma unroll 1
    for (int ks = 0; ks < 16; ++ks) {
        uint32_t a[4][4], b[8][2];
        load_a4<528>(sA, wm * 64, ks * 16, lane, a);
        load_b<528>(sB, wn * 64, ks * 16, lane, b);
#pragma unroll
        for (int fm = 0; fm < 4; ++fm)
#pragma unroll
            for (int fn = 0; fn < 8; ++fn) mma16816(acc[fm][fn], a[fm], b[fn]);
    }
    bf16* Og = g_tri + (size_t)p * 65536 + (size_t)ti * 32768;
#pragma unroll
    for (int fm = 0; fm < 4; ++fm)
#pragma unroll
        for (int fn = 0; fn < 8; ++fn)
#pragma unroll
            for (int cp = 0; cp < 2; ++cp) {
                int row = wm * 64 + fm * 16 + (lane >> 2) + cp * 8;
                int col = wn * 64 + fn * 8 + ((lane & 3) << 1);
                *(__nv_bfloat162*)&Og[(size_t)row * 256 + col] =
                    __floats2bfloat162_rn(acc[fm][fn][2 * cp], acc[fm][fn][2 * cp + 1]);
            }
}

// ---------------- K3: LN over h + gate + fused 3-term output GEMM (512 thr) -------
// grid (2 jt, 512 bi). V stored [h][j]; A via ldmatrix.trans. Warp tile 32x32.
#define K3_SMEM (4 * 34816 + 2 * 16 * 132 * 4 + 1024)
__global__ void __launch_bounds__(512, 1)
k3_out(const float* __restrict__ onw, const float* __restrict__ onb,
       float* __restrict__ out) {
    extern __shared__ char sm[];
    bf16* Vhi = (bf16*)sm;             // [h=128][j=128] stride 136 (raw tri, then hi)
    bf16* Vlo = Vhi + 128 * 136;
    bf16* Whi = Vlo + 128 * 136;       // w_out [dim][hid] stride 136
    bf16* Wlo = Whi + 128 * 136;
    float* red1 = (float*)(sm + 4 * 34816);          // [16][132]
    float* red2 = red1 + 16 * 132;
    float* smu = red2 + 16 * 132;                    // [128]
    float* srs = smu + 128;
    const int tid = threadIdx.x, lane = tid & 31, wid = tid >> 5;
    const int jt = blockIdx.x, bi = blockIdx.y;
    const int b = bi >> 8, i = bi & 255, j0g = jt * 128;

#pragma unroll
    for (int it = 0; it < 4; ++it) {
        int idx = it * 512 + tid, h = idx >> 4, c8 = (idx & 15) << 3;
        *(uint4*)(Vhi + h * 136 + c8) =
            *(const uint4*)&g_tri[(((size_t)b * 128 + h) * 256 + i) * 256 + j0g + c8];
        *(uint4*)(Whi + h * 136 + c8) = *(const uint4*)(g_whi + 5 * 16384 + h * 128 + c8);
        *(uint4*)(Wlo + h * 136 + c8) = *(const uint4*)(g_wlo + 5 * 16384 + h * 128 + c8);
    }
    __syncthreads();
    // LN stats over h: per-warp partial sums, conflict-free row reads
    {
        float s1[4] = {0.f, 0.f, 0.f, 0.f}, s2[4] = {0.f, 0.f, 0.f, 0.f};
#pragma unroll
        for (int r = 0; r < 8; ++r) {
            int h = wid * 8 + r;
            uint2 raw = *(const uint2*)(Vhi + h * 136 + 4 * lane);
            float2 p0 = __bfloat1622float2(*(__nv_bfloat162*)&raw.x);
            float2 p1 = __bfloat1622float2(*(__nv_bfloat162*)&raw.y);
            s1[0] += p0.x; s2[0] += p0.x * p0.x;
            s1[1] += p0.y; s2[1] += p0.y * p0.y;
            s1[2] += p1.x; s2[2] += p1.x * p1.x;
            s1[3] += p1.y; s2[3] += p1.y * p1.y;
        }
        *(float4*)(red1 + wid * 132 + 4 * lane) = make_float4(s1[0], s1[1], s1[2], s1[3]);
        *(float4*)(red2 + wid * 132 + 4 * lane) = make_float4(s2[0], s2[1], s2[2], s2[3]);
    }
    __syncthreads();
    if (tid < 128) {
        float a = 0.f, c = 0.f;
#pragma unroll
        for (int w = 0; w < 16; ++w) { a += red1[w * 132 + tid]; c += red2[w * 132 + tid]; }
        float mu = a * 0.0078125f;
        float var = c * 0.0078125f - mu * mu;
        smu[tid] = mu;
        srs[tid] = rsqrtf(fmaxf(var, 0.f) + 1e-5f);
    }
    __syncthreads();
    // normalize + gate, in place, hi/lo split; gate read coalesced from global
    {
        const float4 mu4 = *(const float4*)(smu + 4 * lane);
        const float4 rs4 = *(const float4*)(srs + 4 * lane);
#pragma unroll
        for (int r = 0; r < 8; ++r) {
            int h = wid * 8 + r;
            float wn_ = __ldg(onw + h), bb_ = __ldg(onb + h);
            float4 g4 = *(const float4*)&g_gate[((size_t)bi * 128 + h) * 256 + j0g + 4 * lane];
            uint2 raw = *(const uint2*)(Vhi + h * 136 + 4 * lane);
            float2 p0 = __bfloat1622float2(*(__nv_bfloat162*)&raw.x);
            float2 p1 = __bfloat1622float2(*(__nv_bfloat162*)&raw.y);
            float v0 = ((p0.x - mu4.x) * rs4.x * wn_ + bb_) * g4.x;
            float v1 = ((p0.y - mu4.y) * rs4.y * wn_ + bb_) * g4.y;
            float v2 = ((p1.x - mu4.z) * rs4.z * wn_ + bb_) * g4.z;
            float v3 = ((p1.y - mu4.w) * rs4.w * wn_ + bb_) * g4.w;
            __nv_bfloat162 h0 = __floats2bfloat162_rn(v0, v1);
            __nv_bfloat162 h1 = __floats2bfloat162_rn(v2, v3);
            float2 q0 = __bfloat1622float2(h0), q1 = __bfloat1622float2(h1);
            uint2 hp, lp;
            *(__nv_bfloat162*)&hp.x = h0;
            *(__nv_bfloat162*)&hp.y = h1;
            *(__nv_bfloat162*)&lp.x = __floats2bfloat162_rn(v0 - q0.x, v1 - q0.y);
            *(__nv_bfloat162*)&lp.y = __floats2bfloat162_rn(v2 - q1.x, v3 - q1.y);
            *(uint2*)(Vhi + h * 136 + 4 * lane) = hp;
            *(uint2*)(Vlo + h * 136 + 4 * lane) = lp;
        }
    }
    __syncthreads();
    // Fused 3-term GEMM: out[j][dim] = Vhi*Whi^T + Vhi*Wlo^T + Vlo*Whi^T
    const int wm = wid & 3, wn = wid >> 2;  // m: 4x32 j, n: 4x32 dim
    const int m0 = wm * 32, n0 = wn * 32;
    const uint32_t sVh = cvta_s(Vhi), sVl = cvta_s(Vlo);
    const uint32_t sWh = cvta_s(Whi), sWl = cvta_s(Wlo);
    float acc[2][4][4];
    ZERO_ACC44(acc);
#pragma unroll
    for (int ks = 0; ks < 8; ++ks) {
        uint32_t ah[2][4], al[2][4], bh[4][2], bl[4][2];
        load_at<272>(sVh, m0, ks * 16, lane, ah);
        load_b32<272>(sWh, n0, ks * 16, lane, bh);
        load_at<272>(sVl, m0, ks * 16, lane, al);
        load_b32<272>(sWl, n0, ks * 16, lane, bl);
        mma8(acc, ah, bh);
        mma8(acc, ah, bl);
        mma8(acc, al, bh);
    }
    float* Ob = out + ((size_t)bi * 256 + j0g) * 128;
#pragma unroll
    for (int fm = 0; fm < 2; ++fm)
#pragma unroll
        for (int fn = 0; fn < 4; ++fn)
#pragma unroll
            for (int cp = 0; cp < 2; ++cp) {
                int row = m0 + fm * 16 + (lane >> 2) + cp * 8;  // j
                int col = n0 + fn * 8 + ((lane & 3) << 1);      // dim
                *(float2*)&Ob[(size_t)row * 128 + col] =
                    make_float2(acc[fm][fn][2 * cp], acc[fm][fn][2 * cp + 1]);
            }
}

extern "C" void kernel_launch(void* const* d_in, const int* in_sizes, int n_in,
                              void* d_out, int out_size) {
    const float* x    = (const float*)d_in[0];
    const float* mask = (const float*)d_in[1];
    const float* nw   = (const float*)d_in[2];
    const float* nb   = (const float*)d_in[3];
    const float* wl   = (const float*)d_in[4];
    const float* wr   = (const float*)d_in[5];
    const float* wlg  = (const float*)d_in[6];
    const float* wrg  = (const float*)d_in[7];
    const float* wog  = (const float*)d_in[8];
    const float* onw  = (const float*)d_in[9];
    const float* onb  = (const float*)d_in[10];
    const float* wout = (const float*)d_in[11];
    float* out = (float*)d_out;

    static bool attr_done = false;
    if (!attr_done) {
        cudaFuncSetAttribute(k1_proj, cudaFuncAttributeMaxDynamicSharedMemorySize, K1_SMEM);
        cudaFuncSetAttribute(k2_tri, cudaFuncAttributeMaxDynamicSharedMemorySize, K2_SMEM);
        cudaFuncSetAttribute(k3_out, cudaFuncAttributeMaxDynamicSharedMemorySize, K3_SMEM);
        attr_done = true;
    }
    k0_prep<<<6, 256>>>(wl, wr, wlg, wrg, wog, wout);
    k1_proj<<<dim3(2, 512), 512, K1_SMEM>>>(x, mask, nw, nb);
    k2_tri<<<dim3(2, 256), 256, K2_SMEM>>>();
    k3_out<<<dim3(2, 512), 512, K3_SMEM>>>(onw, onb, out);
}

// round 12
// speedup vs baseline: 2.1782x; 1.2510x over previous
#include <cuda_runtime.h>
#include <cuda_bf16.h>
#include <cstdint>
#include <math.h>

using bf16 = __nv_bfloat16;
#define BB 2
#define SSZ 256

// scratch (device globals; no cudaMalloc allowed)
__device__ bf16  g_left [(size_t)BB * 128 * SSZ * SSZ];  // [b][h][i][k]
__device__ bf16  g_right[(size_t)BB * 128 * SSZ * SSZ];  // [b][h][j][k]
__device__ bf16  g_tri  [(size_t)BB * 128 * SSZ * SSZ];  // [b][h][i][j]
__device__ float g_gate [(size_t)BB * SSZ * SSZ * 128];  // [b][i][h][j]
// pre-fragmented weights (ldmatrix-equivalent layout)
// A-operand frags: [mat 0..4][term hi/lo][ks][m16][lane][q]
__device__ uint32_t g_wfA[5][2][8][8][32][4];
// B-operand frags for w_out: [term][ks][n16][lane][q]
__device__ uint32_t g_wfB[2][8][8][32][4];

static __device__ __forceinline__ uint32_t cvta_s(const void* p) {
    return (uint32_t)__cvta_generic_to_shared(p);
}
static __device__ __forceinline__ void ldsm4(uint32_t a, uint32_t& r0, uint32_t& r1,
                                             uint32_t& r2, uint32_t& r3) {
    asm volatile("ldmatrix.sync.aligned.m8n8.x4.shared.b16 {%0,%1,%2,%3},[%4];"
                 : "=r"(r0), "=r"(r1), "=r"(r2), "=r"(r3) : "r"(a));
}
static __device__ __forceinline__ void ldsm4t(uint32_t a, uint32_t& r0, uint32_t& r1,
                                              uint32_t& r2, uint32_t& r3) {
    asm volatile("ldmatrix.sync.aligned.m8n8.x4.trans.shared.b16 {%0,%1,%2,%3},[%4];"
                 : "=r"(r0), "=r"(r1), "=r"(r2), "=r"(r3) : "r"(a));
}
static __device__ __forceinline__ void mma16816(float* c, const uint32_t* a,
                                                const uint32_t* b) {
    asm volatile(
        "mma.sync.aligned.m16n8k16.row.col.f32.bf16.bf16.f32 "
        "{%0,%1,%2,%3},{%4,%5,%6,%7},{%8,%9},{%0,%1,%2,%3};"
        : "+f"(c[0]), "+f"(c[1]), "+f"(c[2]), "+f"(c[3])
        : "r"(a[0]), "r"(a[1]), "r"(a[2]), "r"(a[3]), "r"(b[0]), "r"(b[1]));
}
template <int SB>  // A from transposed storage [k][m] (ldmatrix.trans), 32 m-cols
static __device__ __forceinline__ void load_at(uint32_t base, int m0, int k0, int lane,
                                               uint32_t a[2][4]) {
#pragma unroll
    for (int fm = 0; fm < 2; ++fm) {
        int row = k0 + (lane & 7) + ((lane >> 4) << 3);
        int col = m0 + fm * 16 + (lane & 8);
        ldsm4t(base + row * SB + col * 2, a[fm][0], a[fm][1], a[fm][2], a[fm][3]);
    }
}
template <int SB>  // 4 m16 frags (64 rows)
static __device__ __forceinline__ void load_a4(uint32_t base, int m0, int k0, int lane,
                                               uint32_t a[4][4]) {
#pragma unroll
    for (int fm = 0; fm < 4; ++fm) {
        int row = m0 + fm * 16 + (lane & 15), col = k0 + ((lane >> 4) << 3);
        ldsm4(base + row * SB + col * 2, a[fm][0], a[fm][1], a[fm][2], a[fm][3]);
    }
}
template <int SB>  // B operand, 64 n-rows (8 frags)
static __device__ __forceinline__ void load_b(uint32_t base, int n0, int k0, int lane,
                                              uint32_t b[8][2]) {
#pragma unroll
    for (int q = 0; q < 4; ++q) {
        int row = n0 + q * 16 + (lane & 7) + ((lane >> 4) << 3);
        int col = k0 + (((lane >> 3) & 1) << 3);
        ldsm4(base + row * SB + col * 2, b[2 * q][0], b[2 * q][1],
              b[2 * q + 1][0], b[2 * q + 1][1]);
    }
}
template <int SB>  // B operand, 32 n-rows (4 frags)
static __device__ __forceinline__ void load_b32(uint32_t base, int n0, int k0, int lane,
                                                uint32_t b[4][2]) {
#pragma unroll
    for (int q = 0; q < 2; ++q) {
        int row = n0 + q * 16 + (lane & 7) + ((lane >> 4) << 3);
        int col = k0 + (((lane >> 3) & 1) << 3);
        ldsm4(base + row * SB + col * 2, b[2 * q][0], b[2 * q][1],
              b[2 * q + 1][0], b[2 * q + 1][1]);
    }
}
static __device__ __forceinline__ void mma8(float acc[2][4][4], const uint32_t a[2][4],
                                            const uint32_t b[4][2]) {
#pragma unroll
    for (int fm = 0; fm < 2; ++fm)
#pragma unroll
        for (int fn = 0; fn < 4; ++fn) mma16816(acc[fm][fn], a[fm], b[fn]);
}
// load A-operand frag pair (32 m-rows) from prepacked global
static __device__ __forceinline__ void load_wfA(int mat, int term, int ks, int m16a,
                                                int lane, uint32_t a[2][4]) {
    uint4 p0 = *(const uint4*)&g_wfA[mat][term][ks][m16a][lane][0];
    uint4 p1 = *(const uint4*)&g_wfA[mat][term][ks][m16a + 1][lane][0];
    a[0][0] = p0.x; a[0][1] = p0.y; a[0][2] = p0.z; a[0][3] = p0.w;
    a[1][0] = p1.x; a[1][1] = p1.y; a[1][2] = p1.z; a[1][3] = p1.w;
}
// load B-operand frags (32 n-rows) from prepacked global
static __device__ __forceinline__ void load_wfB(int term, int ks, int n16a, int lane,
                                                uint32_t b[4][2]) {
#pragma unroll
    for (int q2 = 0; q2 < 2; ++q2) {
        uint4 w = *(const uint4*)&g_wfB[term][ks][n16a + q2][lane][0];
        b[2 * q2][0] = w.x; b[2 * q2][1] = w.y;
        b[2 * q2 + 1][0] = w.z; b[2 * q2 + 1][1] = w.w;
    }
}
static __device__ __forceinline__ float warpsum(float v) {
#pragma unroll
    for (int o = 16; o > 0; o >>= 1) v += __shfl_xor_sync(0xffffffffu, v, o);
    return v;
}
static __device__ __forceinline__ float sigmoidf_(float g) {
    return 1.0f / (1.0f + __expf(-g));
}
#define ZERO_ACC44(acc)                                         \
    {                                                           \
        _Pragma("unroll") for (int z1 = 0; z1 < 2; ++z1)        \
            _Pragma("unroll") for (int z2 = 0; z2 < 4; ++z2)    \
                _Pragma("unroll") for (int z3 = 0; z3 < 4; ++z3)\
                    acc[z1][z2][z3] = 0.f;                      \
    }

// ---------------- K0: pack weights into mma fragment layout ----------------
// grid 12: blocks 0-9 -> A-frags (mat=bx>>1, term=bx&1); 10-11 -> B-frags (w_out)
__global__ void k0_prep(const float* wl, const float* wr, const float* wlg,
                        const float* wrg, const float* wog, const float* wout) {
    const float* srcsA[5] = {wl, wr, wlg, wrg, wog};
    int bx = blockIdx.x;
    bool isB = bx >= 10;
    const float* src = isB ? wout : srcsA[bx >> 1];
    int term = isB ? (bx - 10) : (bx & 1);
    for (int idx = threadIdx.x; idx < 8192; idx += 256) {
        int ks = idx >> 10, rem = idx & 1023;
        int g16 = rem >> 7, rem2 = rem & 127;
        int lane = rem2 >> 2, q = rem2 & 3;
        int row, col;
        if (!isB) {  // A: q bit0 -> row+8, bit1 -> col+8
            row = g16 * 16 + (lane >> 2) + (q & 1) * 8;
            col = ks * 16 + 2 * (lane & 3) + (q >> 1) * 8;
        } else {     // B: q bit0 -> col+8, bit1 -> row+8
            row = g16 * 16 + (lane >> 2) + (q >> 1) * 8;
            col = ks * 16 + 2 * (lane & 3) + (q & 1) * 8;
        }
        float v0 = src[row * 128 + col], v1 = src[row * 128 + col + 1];
        bf16 o0, o1;
        if (term == 0) { o0 = __float2bfloat16(v0); o1 = __float2bfloat16(v1); }
        else {
            o0 = __float2bfloat16(v0 - __bfloat162float(__float2bfloat16(v0)));
            o1 = __float2bfloat16(v1 - __bfloat162float(__float2bfloat16(v1)));
        }
        uint32_t word;
        __nv_bfloat162 pk(o0, o1);
        word = *(uint32_t*)&pk;
        if (!isB) g_wfA[bx >> 1][term][ks][g16][lane][q] = word;
        else      g_wfB[term][ks][g16][lane][q] = word;
    }
}

// ---------------- K1: LN + 5 projections + gating (frag-LDG weights) ----------
// grid (2 kt, 512 bi), 512 thr. Warp tile 32x32; wm=wid>>2 (share W lines).
// merged 3-term loop: (Whi+Wlo)*Xhi + Whi*Xlo for proj AND gate.
#define K1_SMEM (2 * 34816 + 512)
__global__ void __launch_bounds__(512, 1)
k1_proj(const float* __restrict__ x, const float* __restrict__ mask,
        const float* __restrict__ nw, const float* __restrict__ nb) {
    extern __shared__ char sm[];
    bf16* Ahi = (bf16*)sm;           // Xn_hi [k=128][d=128] stride 136
    bf16* Alo = Ahi + 128 * 136;     // Xn_lo
    float* msk = (float*)(sm + 2 * 34816);
    const int tid = threadIdx.x, lane = tid & 31, wid = tid >> 5;
    const int kt = blockIdx.x, bi = blockIdx.y;
    const int b = bi >> 8, i = bi & 255, k0g = kt * 128;

    if (tid < 128) msk[tid] = mask[(size_t)bi * 256 + k0g + tid];
    const float4 nwv = reinterpret_cast<const float4*>(nw)[lane];
    const float4 nbv = reinterpret_cast<const float4*>(nb)[lane];
    for (int r = wid * 8; r < wid * 8 + 8; ++r) {
        const float4 v = reinterpret_cast<const float4*>(
            x + ((size_t)bi * 256 + k0g + r) * 128)[lane];
        float mu = warpsum(v.x + v.y + v.z + v.w) * 0.0078125f;
        float dx = v.x - mu, dy = v.y - mu, dz = v.z - mu, dw = v.w - mu;
        float rs = rsqrtf(warpsum(dx * dx + dy * dy + dz * dz + dw * dw) * 0.0078125f + 1e-5f);
        float f0 = dx * rs * nwv.x + nbv.x, f1 = dy * rs * nwv.y + nbv.y;
        float f2 = dz * rs * nwv.z + nbv.z, f3 = dw * rs * nwv.w + nbv.w;
        bf16 h0 = __float2bfloat16(f0), h1 = __float2bfloat16(f1);
        bf16 h2 = __float2bfloat16(f2), h3 = __float2bfloat16(f3);
        __nv_bfloat162* ph = (__nv_bfloat162*)(Ahi + r * 136 + lane * 4);
        ph[0] = __nv_bfloat162(h0, h1);
        ph[1] = __nv_bfloat162(h2, h3);
        __nv_bfloat162* pl = (__nv_bfloat162*)(Alo + r * 136 + lane * 4);
        pl[0] = __nv_bfloat162(__float2bfloat16(f0 - __bfloat162float(h0)),
                               __float2bfloat16(f1 - __bfloat162float(h1)));
        pl[1] = __nv_bfloat162(__float2bfloat16(f2 - __bfloat162float(h2)),
                               __float2bfloat16(f3 - __bfloat162float(h3)));
    }
    __syncthreads();
    const uint32_t sAh = cvta_s(Ahi), sAl = cvta_s(Alo);
    const int wm = wid >> 2, wn = wid & 3;  // consecutive warps share wm -> W L1 hits
    const int m0 = wm * 32, n0 = wn * 32, m16a = wm * 2;

#pragma unroll 1
    for (int pass = 0; pass < 2; ++pass) {
        const int mat = pass, gmat = 2 + pass;
        float accP[2][4][4], accG[2][4][4];
        ZERO_ACC44(accP); ZERO_ACC44(accG);
#pragma unroll
        for (int ks = 0; ks < 8; ++ks) {
            uint32_t bh[4][2], bl[4][2], a0[2][4], a1[2][4];
            load_b32<272>(sAh, n0, ks * 16, lane, bh);
            load_b32<272>(sAl, n0, ks * 16, lane, bl);
            load_wfA(mat, 0, ks, m16a, lane, a0);
            load_wfA(mat, 1, ks, m16a, lane, a1);
            mma8(accP, a0, bh);   // Whi*Xhi
            mma8(accP, a1, bh);   // Wlo*Xhi
            mma8(accP, a0, bl);   // Whi*Xlo
            load_wfA(gmat, 0, ks, m16a, lane, a0);
            load_wfA(gmat, 1, ks, m16a, lane, a1);
            mma8(accG, a0, bh);
            mma8(accG, a1, bh);
            mma8(accG, a0, bl);
        }
        bf16* dst = pass == 0 ? g_left : g_right;
#pragma unroll
        for (int fm = 0; fm < 2; ++fm)
#pragma unroll
            for (int fn = 0; fn < 4; ++fn)
#pragma unroll
                for (int cp = 0; cp < 2; ++cp) {
                    int row = m0 + fm * 16 + (lane >> 2) + cp * 8;  // out_ch h
                    int col = n0 + fn * 8 + ((lane & 3) << 1);      // k
                    float2 mk = *(float2*)(msk + col);
                    float v0 = accP[fm][fn][2 * cp] * mk.x * sigmoidf_(accG[fm][fn][2 * cp]);
                    float v1 = accP[fm][fn][2 * cp + 1] * mk.y *
                               sigmoidf_(accG[fm][fn][2 * cp + 1]);
                    *(__nv_bfloat162*)&dst[(((size_t)b * 128 + row) * 256 + i) * 256 +
                                           k0g + col] = __floats2bfloat162_rn(v0, v1);
                }
    }
    // out-gate pass (3-term), store fp32 sigmoid -> g_gate[b][i][h][j]
    {
        float accG[2][4][4];
        ZERO_ACC44(accG);
#pragma unroll
        for (int ks = 0; ks < 8; ++ks) {
            uint32_t bh[4][2], bl[4][2], a0[2][4], a1[2][4];
            load_b32<272>(sAh, n0, ks * 16, lane, bh);
            load_b32<272>(sAl, n0, ks * 16, lane, bl);
            load_wfA(4, 0, ks, m16a, lane, a0);
            load_wfA(4, 1, ks, m16a, lane, a1);
            mma8(accG, a0, bh);
            mma8(accG, a1, bh);
            mma8(accG, a0, bl);
        }
#pragma unroll
        for (int fm = 0; fm < 2; ++fm)
#pragma unroll
            for (int fn = 0; fn < 4; ++fn)
#pragma unroll
                for (int cp = 0; cp < 2; ++cp) {
                    int row = m0 + fm * 16 + (lane >> 2) + cp * 8;  // h
                    int col = n0 + fn * 8 + ((lane & 3) << 1);      // j(=k)
                    *(float2*)&g_gate[((size_t)bi * 128 + row) * 256 + k0g + col] =
                        make_float2(sigmoidf_(accG[fm][fn][2 * cp]),
                                    sigmoidf_(accG[fm][fn][2 * cp + 1]));
                }
    }
}

// ---------------- K2: batched 256^3 bf16 NT GEMM, k fully resident ----------------
// grid (2 ti, 256 p), 256 thr; block out = 128i x 256j; warp tile 64x64
#define K2_SMEM (128 * 264 * 2 + 256 * 264 * 2)
__global__ void __launch_bounds__(256, 1) k2_tri() {
    extern __shared__ char sm[];
    bf16* As = (bf16*)sm;            // [128][264]
    bf16* Bs = As + 128 * 264;       // [256][264]
    const int tid = threadIdx.x, lane = tid & 31, wid = tid >> 5;
    const int wm = wid & 1, wn = wid >> 1;  // 2x64 m, 4x64 n
    const int p = blockIdx.y, ti = blockIdx.x;
    const uint4* Lg = (const uint4*)(g_left + (size_t)p * 65536 + (size_t)ti * 32768);
    const uint4* Rg = (const uint4*)(g_right + (size_t)p * 65536);
#pragma unroll
    for (int it = 0; it < 16; ++it) {
        int idx = it * 256 + tid, r = idx >> 5, c8 = (idx & 31) << 3;
        *(uint4*)(As + r * 264 + c8) = Lg[idx];
    }
#pragma unroll
    for (int it = 0; it < 32; ++it) {
        int idx = it * 256 + tid, r = idx >> 5, c8 = (idx & 31) << 3;
        *(uint4*)(Bs + r * 264 + c8) = Rg[idx];
    }
    __syncthreads();
    const uint32_t sA = cvta_s(As), sB = cvta_s(Bs);
    float acc[4][8][4];
#pragma unroll
    for (int z1 = 0; z1 < 4; ++z1)
#pragma unroll
        for (int z2 = 0; z2 < 8; ++z2)
#pragma unroll
            for (int z3 = 0; z3 < 4; ++z3) acc[z1][z2][z3] = 0.f;
#pragma unroll 1
    for (int ks = 0; ks < 16; ++ks) {
        uint32_t a[4][4], b[8][2];
        load_a4<528>(sA, wm * 64, ks * 16, lane, a);
        load_b<528>(sB, wn * 64, ks * 16, lane, b);
#pragma unroll
        for (int fm = 0; fm < 4; ++fm)
#pragma unroll
            for (int fn = 0; fn < 8; ++fn) mma16816(acc[fm][fn], a[fm], b[fn]);
    }
    bf16* Og = g_tri + (size_t)p * 65536 + (size_t)ti * 32768;
#pragma unroll
    for (int fm = 0; fm < 4; ++fm)
#pragma unroll
        for (int fn = 0; fn < 8; ++fn)
#pragma unroll
            for (int cp = 0; cp < 2; ++cp) {
                int row = wm * 64 + fm * 16 + (lane >> 2) + cp * 8;
                int col = wn * 64 + fn * 8 + ((lane & 3) << 1);
                *(__nv_bfloat162*)&Og[(size_t)row * 256 + col] =
                    __floats2bfloat162_rn(acc[fm][fn][2 * cp], acc[fm][fn][2 * cp + 1]);
            }
}

// ---------------- K3: LN over h + gate + fused 3-term output GEMM ----------------
// grid (2 jt, 512 bi), 512 thr. V [h][j] in smem (ldsm.trans); w_out via frag LDG.
#define K3_SMEM (2 * 34816 + 2 * 16 * 132 * 4 + 1024)
__global__ void __launch_bounds__(512, 1)
k3_out(const float* __restrict__ onw, const float* __restrict__ onb,
       float* __restrict__ out) {
    extern __shared__ char sm[];
    bf16* Vhi = (bf16*)sm;             // [h=128][j=128] stride 136
    bf16* Vlo = Vhi + 128 * 136;
    float* red1 = (float*)(sm + 2 * 34816);          // [16][132]
    float* red2 = red1 + 16 * 132;
    float* smu = red2 + 16 * 132;                    // [128]
    float* srs = smu + 128;
    const int tid = threadIdx.x, lane = tid & 31, wid = tid >> 5;
    const int jt = blockIdx.x, bi = blockIdx.y;
    const int b = bi >> 8, i = bi & 255, j0g = jt * 128;

#pragma unroll
    for (int it = 0; it < 4; ++it) {
        int idx = it * 512 + tid, h = idx >> 4, c8 = (idx & 15) << 3;
        *(uint4*)(Vhi + h * 136 + c8) =
            *(const uint4*)&g_tri[(((size_t)b * 128 + h) * 256 + i) * 256 + j0g + c8];
    }
    __syncthreads();
    // LN stats over h: per-warp partial sums, conflict-free row reads
    {
        float s1[4] = {0.f, 0.f, 0.f, 0.f}, s2[4] = {0.f, 0.f, 0.f, 0.f};
#pragma unroll
        for (int r = 0; r < 8; ++r) {
            int h = wid * 8 + r;
            uint2 raw = *(const uint2*)(Vhi + h * 136 + 4 * lane);
            float2 p0 = __bfloat1622float2(*(__nv_bfloat162*)&raw.x);
            float2 p1 = __bfloat1622float2(*(__nv_bfloat162*)&raw.y);
            s1[0] += p0.x; s2[0] += p0.x * p0.x;
            s1[1] += p0.y; s2[1] += p0.y * p0.y;
            s1[2] += p1.x; s2[2] += p1.x * p1.x;
            s1[3] += p1.y; s2[3] += p1.y * p1.y;
        }
        *(float4*)(red1 + wid * 132 + 4 * lane) = make_float4(s1[0], s1[1], s1[2], s1[3]);
        *(float4*)(red2 + wid * 132 + 4 * lane) = make_float4(s2[0], s2[1], s2[2], s2[3]);
    }
    __syncthreads();
    if (tid < 128) {
        float a = 0.f, c = 0.f;
#pragma unroll
        for (int w = 0; w < 16; ++w) { a += red1[w * 132 + tid]; c += red2[w * 132 + tid]; }
        float mu = a * 0.0078125f;
        float var = c * 0.0078125f - mu * mu;
        smu[tid] = mu;
        srs[tid] = rsqrtf(fmaxf(var, 0.f) + 1e-5f);
    }
    __syncthreads();
    // normalize + gate, in place, hi/lo split; gate read coalesced from global
    {
        const float4 mu4 = *(const float4*)(smu + 4 * lane);
        const float4 rs4 = *(const float4*)(srs + 4 * lane);
#pragma unroll
        for (int r = 0; r < 8; ++r) {
            int h = wid * 8 + r;
            float wn_ = __ldg(onw + h), bb_ = __ldg(onb + h);
            float4 g4 = *(const float4*)&g_gate[((size_t)bi * 128 + h) * 256 + j0g + 4 * lane];
            uint2 raw = *(const uint2*)(Vhi + h * 136 + 4 * lane);
            float2 p0 = __bfloat1622float2(*(__nv_bfloat162*)&raw.x);
            float2 p1 = __bfloat1622float2(*(__nv_bfloat162*)&raw.y);
            float v0 = ((p0.x - mu4.x) * rs4.x * wn_ + bb_) * g4.x;
            float v1 = ((p0.y - mu4.y) * rs4.y * wn_ + bb_) * g4.y;
            float v2 = ((p1.x - mu4.z) * rs4.z * wn_ + bb_) * g4.z;
            float v3 = ((p1.y - mu4.w) * rs4.w * wn_ + bb_) * g4.w;
            __nv_bfloat162 h0 = __floats2bfloat162_rn(v0, v1);
            __nv_bfloat162 h1 = __floats2bfloat162_rn(v2, v3);
            float2 q0 = __bfloat1622float2(h0), q1 = __bfloat1622float2(h1);
            uint2 hp, lp;
            *(__nv_bfloat162*)&hp.x = h0;
            *(__nv_bfloat162*)&hp.y = h1;
            *(__nv_bfloat162*)&lp.x = __floats2bfloat162_rn(v0 - q0.x, v1 - q0.y);
            *(__nv_bfloat162*)&lp.y = __floats2bfloat162_rn(v2 - q1.x, v3 - q1.y);
            *(uint2*)(Vhi + h * 136 + 4 * lane) = hp;
            *(uint2*)(Vlo + h * 136 + 4 * lane) = lp;
        }
    }
    __syncthreads();
    // Fused 3-term GEMM: out[j][dim] = Vhi*Whi^T + Vhi*Wlo^T + Vlo*Whi^T
    const int wm = wid & 3, wn = wid >> 2;  // consecutive warps share wn -> W L1 hits
    const int m0 = wm * 32, n0 = wn * 32, n16a = wn * 2;
    const uint32_t sVh = cvta_s(Vhi), sVl = cvta_s(Vlo);
    float acc[2][4][4];
    ZERO_ACC44(acc);
#pragma unroll
    for (int ks = 0; ks < 8; ++ks) {
        uint32_t ah[2][4], al[2][4], bh[4][2], bl[4][2];
        load_at<272>(sVh, m0, ks * 16, lane, ah);
        load_at<272>(sVl, m0, ks * 16, lane, al);
        load_wfB(0, ks, n16a, lane, bh);
        load_wfB(1, ks, n16a, lane, bl);
        mma8(acc, ah, bh);
        mma8(acc, ah, bl);
        mma8(acc, al, bh);
    }
    float* Ob = out + ((size_t)bi * 256 + j0g) * 128;
#pragma unroll
    for (int fm = 0; fm < 2; ++fm)
#pragma unroll
        for (int fn = 0; fn < 4; ++fn)
#pragma unroll
            for (int cp = 0; cp < 2; ++cp) {
                int row = m0 + fm * 16 + (lane >> 2) + cp * 8;  // j
                int col = n0 + fn * 8 + ((lane & 3) << 1);      // dim
                *(float2*)&Ob[(size_t)row * 128 + col] =
                    make_float2(acc[fm][fn][2 * cp], acc[fm][fn][2 * cp + 1]);
            }
}

extern "C" void kernel_launch(void* const* d_in, const int* in_sizes, int n_in,
                              void* d_out, int out_size) {
    const float* x    = (const float*)d_in[0];
    const float* mask = (const float*)d_in[1];
    const float* nw   = (const float*)d_in[2];
    const float* nb   = (const float*)d_in[3];
    const float* wl   = (const float*)d_in[4];
    const float* wr   = (const float*)d_in[5];
    const float* wlg  = (const float*)d_in[6];
    const float* wrg  = (const float*)d_in[7];
    const float* wog  = (const float*)d_in[8];
    const float* onw  = (const float*)d_in[9];
    const float* onb  = (const float*)d_in[10];
    const float* wout = (const float*)d_in[11];
    float* out = (float*)d_out;

    static bool attr_done = false;
    if (!attr_done) {
        cudaFuncSetAttribute(k1_proj, cudaFuncAttributeMaxDynamicSharedMemorySize, K1_SMEM);
        cudaFuncSetAttribute(k2_tri, cudaFuncAttributeMaxDynamicSharedMemorySize, K2_SMEM);
        cudaFuncSetAttribute(k3_out, cudaFuncAttributeMaxDynamicSharedMemorySize, K3_SMEM);
        attr_done = true;
    }
    k0_prep<<<12, 256>>>(wl, wr, wlg, wrg, wog, wout);
    k1_proj<<<dim3(2, 512), 512, K1_SMEM>>>(x, mask, nw, nb);
    k2_tri<<<dim3(2, 256), 256, K2_SMEM>>>();
    k3_out<<<dim3(2, 512), 512, K3_SMEM>>>(onw, onb, out);
}

// round 15
// speedup vs baseline: 2.2678x; 1.0412x over previous
#include <cuda_runtime.h>
#include <cuda_bf16.h>
#include <cuda_fp16.h>
#include <cstdint>
#include <math.h>

using bf16 = __nv_bfloat16;
#define BB 2
#define SSZ 256

// scratch (device globals; no cudaMalloc allowed)
__device__ bf16   g_left [(size_t)BB * 128 * SSZ * SSZ];  // [b][h][i][k]
__device__ bf16   g_right[(size_t)BB * 128 * SSZ * SSZ];  // [b][h][j][k]
__device__ bf16   g_tri  [(size_t)BB * 128 * SSZ * SSZ];  // [b][h][i][j]
__device__ __half g_gate [(size_t)BB * SSZ * SSZ * 128];  // [b][i][h][j] fp16
// pre-fragmented weights (ldmatrix-equivalent layout)
__device__ uint32_t g_wfA[5][2][8][8][32][4];  // [mat][term][ks][m16][lane][q]
__device__ uint32_t g_wfB[2][8][8][32][4];     // w_out B-frags [term][ks][n16][lane][q]

static __device__ __forceinline__ uint32_t cvta_s(const void* p) {
    return (uint32_t)__cvta_generic_to_shared(p);
}
static __device__ __forceinline__ void ldsm4(uint32_t a, uint32_t& r0, uint32_t& r1,
                                             uint32_t& r2, uint32_t& r3) {
    asm volatile("ldmatrix.sync.aligned.m8n8.x4.shared.b16 {%0,%1,%2,%3},[%4];"
                 : "=r"(r0), "=r"(r1), "=r"(r2), "=r"(r3) : "r"(a));
}
static __device__ __forceinline__ void ldsm4t(uint32_t a, uint32_t& r0, uint32_t& r1,
                                              uint32_t& r2, uint32_t& r3) {
    asm volatile("ldmatrix.sync.aligned.m8n8.x4.trans.shared.b16 {%0,%1,%2,%3},[%4];"
                 : "=r"(r0), "=r"(r1), "=r"(r2), "=r"(r3) : "r"(a));
}
static __device__ __forceinline__ void mma16816(float* c, const uint32_t* a,
                                                const uint32_t* b) {
    asm volatile(
        "mma.sync.aligned.m16n8k16.row.col.f32.bf16.bf16.f32 "
        "{%0,%1,%2,%3},{%4,%5,%6,%7},{%8,%9},{%0,%1,%2,%3};"
        : "+f"(c[0]), "+f"(c[1]), "+f"(c[2]), "+f"(c[3])
        : "r"(a[0]), "r"(a[1]), "r"(a[2]), "r"(a[3]), "r"(b[0]), "r"(b[1]));
}
static __device__ __forceinline__ void cpa16(uint32_t d, const void* s) {
    asm volatile("cp.async.cg.shared.global [%0], [%1], 16;" :: "r"(d), "l"(s));
}
#define CPA_COMMIT() asm volatile("cp.async.commit_group;" ::: "memory")
#define CPA_WAIT(n) asm volatile("cp.async.wait_group %0;" :: "n"(n) : "memory")

template <int SB>  // A operand from [m][k] rows, 32 m-rows (2 frags)
static __device__ __forceinline__ void load_a(uint32_t base, int m0, int k0, int lane,
                                              uint32_t a[2][4]) {
#pragma unroll
    for (int fm = 0; fm < 2; ++fm) {
        int row = m0 + fm * 16 + (lane & 15), col = k0 + ((lane >> 4) << 3);
        ldsm4(base + row * SB + col * 2, a[fm][0], a[fm][1], a[fm][2], a[fm][3]);
    }
}
template <int SB>  // A from transposed storage [k][m] (ldmatrix.trans), 32 m-cols
static __device__ __forceinline__ void load_at(uint32_t base, int m0, int k0, int lane,
                                               uint32_t a[2][4]) {
#pragma unroll
    for (int fm = 0; fm < 2; ++fm) {
        int row = k0 + (lane & 7) + ((lane >> 4) << 3);
        int col = m0 + fm * 16 + (lane & 8);
        ldsm4t(base + row * SB + col * 2, a[fm][0], a[fm][1], a[fm][2], a[fm][3]);
    }
}
template <int SB>  // B operand, 64 n-rows (8 frags)
static __device__ __forceinline__ void load_b(uint32_t base, int n0, int k0, int lane,
                                              uint32_t b[8][2]) {
#pragma unroll
    for (int q = 0; q < 4; ++q) {
        int row = n0 + q * 16 + (lane & 7) + ((lane >> 4) << 3);
        int col = k0 + (((lane >> 3) & 1) << 3);
        ldsm4(base + row * SB + col * 2, b[2 * q][0], b[2 * q][1],
              b[2 * q + 1][0], b[2 * q + 1][1]);
    }
}
template <int SB>  // B operand, 32 n-rows (4 frags)
static __device__ __forceinline__ void load_b32(uint32_t base, int n0, int k0, int lane,
                                                uint32_t b[4][2]) {
#pragma unroll
    for (int q = 0; q < 2; ++q) {
        int row = n0 + q * 16 + (lane & 7) + ((lane >> 4) << 3);
        int col = k0 + (((lane >> 3) & 1) << 3);
        ldsm4(base + row * SB + col * 2, b[2 * q][0], b[2 * q][1],
              b[2 * q + 1][0], b[2 * q + 1][1]);
    }
}
static __device__ __forceinline__ void mma8(float acc[2][4][4], const uint32_t a[2][4],
                                            const uint32_t b[4][2]) {
#pragma unroll
    for (int fm = 0; fm < 2; ++fm)
#pragma unroll
        for (int fn = 0; fn < 4; ++fn) mma16816(acc[fm][fn], a[fm], b[fn]);
}
static __device__ __forceinline__ void load_wfA(int mat, int term, int ks, int m16a,
                                                int lane, uint32_t a[2][4]) {
    uint4 p0 = *(const uint4*)&g_wfA[mat][term][ks][m16a][lane][0];
    uint4 p1 = *(const uint4*)&g_wfA[mat][term][ks][m16a + 1][lane][0];
    a[0][0] = p0.x; a[0][1] = p0.y; a[0][2] = p0.z; a[0][3] = p0.w;
    a[1][0] = p1.x; a[1][1] = p1.y; a[1][2] = p1.z; a[1][3] = p1.w;
}
static __device__ __forceinline__ void load_wfB(int term, int ks, int n16a, int lane,
                                                uint32_t b[4][2]) {
#pragma unroll
    for (int q2 = 0; q2 < 2; ++q2) {
        uint4 w = *(const uint4*)&g_wfB[term][ks][n16a + q2][lane][0];
        b[2 * q2][0] = w.x; b[2 * q2][1] = w.y;
        b[2 * q2 + 1][0] = w.z; b[2 * q2 + 1][1] = w.w;
    }
}
static __device__ __forceinline__ float warpsum(float v) {
#pragma unroll
    for (int o = 16; o > 0; o >>= 1) v += __shfl_xor_sync(0xffffffffu, v, o);
    return v;
}
static __device__ __forceinline__ float sigmoidf_(float g) {
    return 1.0f / (1.0f + __expf(-g));
}
#define ZERO_ACC44(acc)                                         \
    {                                                           \
        _Pragma("unroll") for (int z1 = 0; z1 < 2; ++z1)        \
            _Pragma("unroll") for (int z2 = 0; z2 < 4; ++z2)    \
                _Pragma("unroll") for (int z3 = 0; z3 < 4; ++z3)\
                    acc[z1][z2][z3] = 0.f;                      \
    }

// ---------------- K0: pack weights into mma fragment layout ----------------
__global__ void k0_prep(const float* wl, const float* wr, const float* wlg,
                        const float* wrg, const float* wog, const float* wout) {
    const float* srcsA[5] = {wl, wr, wlg, wrg, wog};
    int bx = blockIdx.x;
    bool isB = bx >= 10;
    const float* src = isB ? wout : srcsA[bx >> 1];
    int term = isB ? (bx - 10) : (bx & 1);
    for (int idx = threadIdx.x; idx < 8192; idx += 256) {
        int ks = idx >> 10, rem = idx & 1023;
        int g16 = rem >> 7, rem2 = rem & 127;
        int lane = rem2 >> 2, q = rem2 & 3;
        int row, col;
        if (!isB) {
            row = g16 * 16 + (lane >> 2) + (q & 1) * 8;
            col = ks * 16 + 2 * (lane & 3) + (q >> 1) * 8;
        } else {
            row = g16 * 16 + (lane >> 2) + (q >> 1) * 8;
            col = ks * 16 + 2 * (lane & 3) + (q & 1) * 8;
        }
        float v0 = src[row * 128 + col], v1 = src[row * 128 + col + 1];
        bf16 o0, o1;
        if (term == 0) { o0 = __float2bfloat16(v0); o1 = __float2bfloat16(v1); }
        else {
            o0 = __float2bfloat16(v0 - __bfloat162float(__float2bfloat16(v0)));
            o1 = __float2bfloat16(v1 - __bfloat162float(__float2bfloat16(v1)));
        }
        __nv_bfloat162 pk(o0, o1);
        uint32_t word = *(uint32_t*)&pk;
        if (!isB) g_wfA[bx >> 1][term][ks][g16][lane][q] = word;
        else      g_wfB[term][ks][g16][lane][q] = word;
    }
}

// ---------------- K1: LN + 5 projections + gating (frag-LDG weights) ----------
#define K1_SMEM (2 * 34816 + 512)
__global__ void __launch_bounds__(512, 1)
k1_proj(const float* __restrict__ x, const float* __restrict__ mask,
        const float* __restrict__ nw, const float* __restrict__ nb) {
    extern __shared__ char sm[];
    bf16* Ahi = (bf16*)sm;           // Xn_hi [k=128][d=128] stride 136
    bf16* Alo = Ahi + 128 * 136;     // Xn_lo
    float* msk = (float*)(sm + 2 * 34816);
    const int tid = threadIdx.x, lane = tid & 31, wid = tid >> 5;
    const int kt = blockIdx.x, bi = blockIdx.y;
    const int b = bi >> 8, i = bi & 255, k0g = kt * 128;

    if (tid < 128) msk[tid] = mask[(size_t)bi * 256 + k0g + tid];
    const float4 nwv = reinterpret_cast<const float4*>(nw)[lane];
    const float4 nbv = reinterpret_cast<const float4*>(nb)[lane];
    for (int r = wid * 8; r < wid * 8 + 8; ++r) {
        const float4 v = reinterpret_cast<const float4*>(
            x + ((size_t)bi * 256 + k0g + r) * 128)[lane];
        float mu = warpsum(v.x + v.y + v.z + v.w) * 0.0078125f;
        float dx = v.x - mu, dy = v.y - mu, dz = v.z - mu, dw = v.w - mu;
        float rs = rsqrtf(warpsum(dx * dx + dy * dy + dz * dz + dw * dw) * 0.0078125f + 1e-5f);
        float f0 = dx * rs * nwv.x + nbv.x, f1 = dy * rs * nwv.y + nbv.y;
        float f2 = dz * rs * nwv.z + nbv.z, f3 = dw * rs * nwv.w + nbv.w;
        bf16 h0 = __float2bfloat16(f0), h1 = __float2bfloat16(f1);
        bf16 h2 = __float2bfloat16(f2), h3 = __float2bfloat16(f3);
        __nv_bfloat162* ph = (__nv_bfloat162*)(Ahi + r * 136 + lane * 4);
        ph[0] = __nv_bfloat162(h0, h1);
        ph[1] = __nv_bfloat162(h2, h3);
        __nv_bfloat162* pl = (__nv_bfloat162*)(Alo + r * 136 + lane * 4);
        pl[0] = __nv_bfloat162(__float2bfloat16(f0 - __bfloat162float(h0)),
                               __float2bfloat16(f1 - __bfloat162float(h1)));
        pl[1] = __nv_bfloat162(__float2bfloat16(f2 - __bfloat162float(h2)),
                               __float2bfloat16(f3 - __bfloat162float(h3)));
    }
    __syncthreads();
    const uint32_t sAh = cvta_s(Ahi), sAl = cvta_s(Alo);
    const int wm = wid >> 2, wn = wid & 3;
    const int m0 = wm * 32, n0 = wn * 32, m16a = wm * 2;

#pragma unroll 1
    for (int pass = 0; pass < 2; ++pass) {
        const int mat = pass, gmat = 2 + pass;
        float accP[2][4][4], accG[2][4][4];
        ZERO_ACC44(accP); ZERO_ACC44(accG);
#pragma unroll
        for (int ks = 0; ks < 8; ++ks) {
            uint32_t bh[4][2], bl[4][2], a0[2][4], a1[2][4];
            load_b32<272>(sAh, n0, ks * 16, lane, bh);
            load_b32<272>(sAl, n0, ks * 16, lane, bl);
            load_wfA(mat, 0, ks, m16a, lane, a0);
            load_wfA(mat, 1, ks, m16a, lane, a1);
            mma8(accP, a0, bh);
            mma8(accP, a1, bh);
            mma8(accP, a0, bl);
            load_wfA(gmat, 0, ks, m16a, lane, a0);
            load_wfA(gmat, 1, ks, m16a, lane, a1);
            mma8(accG, a0, bh);
            mma8(accG, a1, bh);
            mma8(accG, a0, bl);
        }
        bf16* dst = pass == 0 ? g_left : g_right;
#pragma unroll
        for (int fm = 0; fm < 2; ++fm)
#pragma unroll
            for (int fn = 0; fn < 4; ++fn)
#pragma unroll
                for (int cp = 0; cp < 2; ++cp) {
                    int row = m0 + fm * 16 + (lane >> 2) + cp * 8;
                    int col = n0 + fn * 8 + ((lane & 3) << 1);
                    float2 mk = *(float2*)(msk + col);
                    float v0 = accP[fm][fn][2 * cp] * mk.x * sigmoidf_(accG[fm][fn][2 * cp]);
                    float v1 = accP[fm][fn][2 * cp + 1] * mk.y *
                               sigmoidf_(accG[fm][fn][2 * cp + 1]);
                    *(__nv_bfloat162*)&dst[(((size_t)b * 128 + row) * 256 + i) * 256 +
                                           k0g + col] = __floats2bfloat162_rn(v0, v1);
                }
    }
    // out-gate pass (3-term), store fp16 sigmoid -> g_gate[b][i][h][j]
    {
        float accG[2][4][4];
        ZERO_ACC44(accG);
#pragma unroll
        for (int ks = 0; ks < 8; ++ks) {
            uint32_t bh[4][2], bl[4][2], a0[2][4], a1[2][4];
            load_b32<272>(sAh, n0, ks * 16, lane, bh);
            load_b32<272>(sAl, n0, ks * 16, lane, bl);
            load_wfA(4, 0, ks, m16a, lane, a0);
            load_wfA(4, 1, ks, m16a, lane, a1);
            mma8(accG, a0, bh);
            mma8(accG, a1, bh);
            mma8(accG, a0, bl);
        }
#pragma unroll
        for (int fm = 0; fm < 2; ++fm)
#pragma unroll
            for (int fn = 0; fn < 4; ++fn)
#pragma unroll
                for (int cp = 0; cp < 2; ++cp) {
                    int row = m0 + fm * 16 + (lane >> 2) + cp * 8;
                    int col = n0 + fn * 8 + ((lane & 3) << 1);
                    *(__half2*)&g_gate[((size_t)bi * 128 + row) * 256 + k0g + col] =
                        __floats2half2_rn(sigmoidf_(accG[fm][fn][2 * cp]),
                                          sigmoidf_(accG[fm][fn][2 * cp + 1]));
                }
    }
}

// ---------------- K2: batched 256^3 bf16 NT GEMM, cp.async double-buffered -------
// grid (2 ti, 256 p), 512 thr; block out = 128i x 256j; warp tile 32x64
// k chunks of 64, 2 buffers: per buffer A[128][72] + B[256][72]
#define K2_BUFELEM 27648
#define K2_SMEM (2 * K2_BUFELEM * 2)
__global__ void __launch_bounds__(512, 1) k2_tri() {
    extern __shared__ char sm[];
    const uint32_t sbase = cvta_s(sm);
    const int tid = threadIdx.x, lane = tid & 31, wid = tid >> 5;
    const int wm = wid & 3, wn = wid >> 2;  // 4x32 m, 4x64 n
    const int p = blockIdx.y, ti = blockIdx.x;
    const bf16* Lg = g_left + (size_t)p * 65536 + (size_t)ti * 32768;
    const bf16* Rg = g_right + (size_t)p * 65536;

    float acc[2][8][4];
#pragma unroll
    for (int z1 = 0; z1 < 2; ++z1)
#pragma unroll
        for (int z2 = 0; z2 < 8; ++z2)
#pragma unroll
            for (int z3 = 0; z3 < 4; ++z3) acc[z1][z2][z3] = 0.f;

    // chunk loader: A 1024 uint4 + B 2048 uint4, 6 cp.async per thread
#define K2_LOAD(c, buf)                                                       \
    {                                                                         \
        uint32_t aB = sbase + (buf) * (K2_BUFELEM * 2);                       \
        uint32_t bB = aB + 9216 * 2;                                          \
        _Pragma("unroll") for (int it = 0; it < 2; ++it) {                    \
            int idx = it * 512 + tid, r = idx >> 3, c8 = (idx & 7) << 3;      \
            cpa16(aB + (r * 72 + c8) * 2, Lg + r * 256 + (c) * 64 + c8);      \
        }                                                                     \
        _Pragma("unroll") for (int it = 0; it < 4; ++it) {                    \
            int idx = it * 512 + tid, r = idx >> 3, c8 = (idx & 7) << 3;      \
            cpa16(bB + (r * 72 + c8) * 2, Rg + r * 256 + (c) * 64 + c8);      \
        }                                                                     \
    }

    K2_LOAD(0, 0); CPA_COMMIT();
#pragma unroll 1
    for (int c = 0; c < 4; ++c) {
        if (c < 3) { K2_LOAD(c + 1, (c + 1) & 1); CPA_COMMIT(); CPA_WAIT(1); }
        else { CPA_WAIT(0); }
        __syncthreads();
        uint32_t sA = sbase + (c & 1) * (K2_BUFELEM * 2);
        uint32_t sB = sA + 9216 * 2;
#pragma unroll
        for (int ks = 0; ks < 4; ++ks) {
            uint32_t a[2][4], b[8][2];
            load_a<144>(sA, wm * 32, ks * 16, lane, a);
            load_b<144>(sB, wn * 64, ks * 16, lane, b);
#pragma unroll
            for (int fm = 0; fm < 2; ++fm)
#pragma unroll
                for (int fn = 0; fn < 8; ++fn) mma16816(acc[fm][fn], a[fm], b[fn]);
        }
        __syncthreads();
    }
#undef K2_LOAD
    bf16* Og = g_tri + (size_t)p * 65536 + (size_t)ti * 32768;
#pragma unroll
    for (int fm = 0; fm < 2; ++fm)
#pragma unroll
        for (int fn = 0; fn < 8; ++fn)
#pragma unroll
            for (int cp = 0; cp < 2; ++cp) {
                int row = wm * 32 + fm * 16 + (lane >> 2) + cp * 8;
                int col = wn * 64 + fn * 8 + ((lane & 3) << 1);
                *(__nv_bfloat162*)&Og[(size_t)row * 256 + col] =
                    __floats2bfloat162_rn(acc[fm][fn][2 * cp], acc[fm][fn][2 * cp + 1]);
            }
}

// ---------------- K3: LN over h + gate + fused 3-term output GEMM ----------------
#define K3_SMEM (2 * 34816 + 2 * 16 * 132 * 4 + 1024)
__global__ void __launch_bounds__(512, 1)
k3_out(const float* __restrict__ onw, const float* __restrict__ onb,
       float* __restrict__ out) {
    extern __shared__ char sm[];
    bf16* Vhi = (bf16*)sm;             // [h=128][j=128] stride 136
    bf16* Vlo = Vhi + 128 * 136;
    float* red1 = (float*)(sm + 2 * 34816);          // [16][132]
    float* red2 = red1 + 16 * 132;
    float* smu = red2 + 16 * 132;                    // [128]
    float* srs = smu + 128;
    const int tid = threadIdx.x, lane = tid & 31, wid = tid >> 5;
    const int jt = blockIdx.x, bi = blockIdx.y;
    const int b = bi >> 8, i = bi & 255, j0g = jt * 128;

#pragma unroll
    for (int it = 0; it < 4; ++it) {
        int idx = it * 512 + tid, h = idx >> 4, c8 = (idx & 15) << 3;
        *(uint4*)(Vhi + h * 136 + c8) =
            *(const uint4*)&g_tri[(((size_t)b * 128 + h) * 256 + i) * 256 + j0g + c8];
    }
    __syncthreads();
    {
        float s1[4] = {0.f, 0.f, 0.f, 0.f}, s2[4] = {0.f, 0.f, 0.f, 0.f};
#pragma unroll
        for (int r = 0; r < 8; ++r) {
            int h = wid * 8 + r;
            uint2 raw = *(const uint2*)(Vhi + h * 136 + 4 * lane);
            float2 p0 = __bfloat1622float2(*(__nv_bfloat162*)&raw.x);
            float2 p1 = __bfloat1622float2(*(__nv_bfloat162*)&raw.y);
            s1[0] += p0.x; s2[0] += p0.x * p0.x;
            s1[1] += p0.y; s2[1] += p0.y * p0.y;
            s1[2] += p1.x; s2[2] += p1.x * p1.x;
            s1[3] += p1.y; s2[3] += p1.y * p1.y;
        }
        *(float4*)(red1 + wid * 132 + 4 * lane) = make_float4(s1[0], s1[1], s1[2], s1[3]);
        *(float4*)(red2 + wid * 132 + 4 * lane) = make_float4(s2[0], s2[1], s2[2], s2[3]);
    }
    __syncthreads();
    if (tid < 128) {
        float a = 0.f, c = 0.f;
#pragma unroll
        for (int w = 0; w < 16; ++w) { a += red1[w * 132 + tid]; c += red2[w * 132 + tid]; }
        float mu = a * 0.0078125f;
        float var = c * 0.0078125f - mu * mu;
        smu[tid] = mu;
        srs[tid] = rsqrtf(fmaxf(var, 0.f) + 1e-5f);
    }
    __syncthreads();
    {
        const float4 mu4 = *(const float4*)(smu + 4 * lane);
        const float4 rs4 = *(const float4*)(srs + 4 * lane);
#pragma unroll
        for (int r = 0; r < 8; ++r) {
            int h = wid * 8 + r;
            float wn_ = __ldg(onw + h), bb_ = __ldg(onb + h);
            uint2 graw = *(const uint2*)&g_gate[((size_t)bi * 128 + h) * 256 + j0g + 4 * lane];
            float2 ga = __half22float2(*(__half2*)&graw.x);
            float2 gb = __half22float2(*(__half2*)&graw.y);
            uint2 raw = *(const uint2*)(Vhi + h * 136 + 4 * lane);
            float2 p0 = __bfloat1622float2(*(__nv_bfloat162*)&raw.x);
            float2 p1 = __bfloat1622float2(*(__nv_bfloat162*)&raw.y);
            float v0 = ((p0.x - mu4.x) * rs4.x * wn_ + bb_) * ga.x;
            float v1 = ((p0.y - mu4.y) * rs4.y * wn_ + bb_) * ga.y;
            float v2 = ((p1.x - mu4.z) * rs4.z * wn_ + bb_) * gb.x;
            float v3 = ((p1.y - mu4.w) * rs4.w * wn_ + bb_) * gb.y;
            __nv_bfloat162 h0 = __floats2bfloat162_rn(v0, v1);
            __nv_bfloat162 h1 = __floats2bfloat162_rn(v2, v3);
            float2 q0 = __bfloat1622float2(h0), q1 = __bfloat1622float2(h1);
            uint2 hp, lp;
            *(__nv_bfloat162*)&hp.x = h0;
            *(__nv_bfloat162*)&hp.y = h1;
            *(__nv_bfloat162*)&lp.x = __floats2bfloat162_rn(v0 - q0.x, v1 - q0.y);
            *(__nv_bfloat162*)&lp.y = __floats2bfloat162_rn(v2 - q1.x, v3 - q1.y);
            *(uint2*)(Vhi + h * 136 + 4 * lane) = hp;
            *(uint2*)(Vlo + h * 136 + 4 * lane) = lp;
        }
    }
    __syncthreads();
    const int wm = wid & 3, wn = wid >> 2;
    const int m0 = wm * 32, n0 = wn * 32, n16a = wn * 2;
    const uint32_t sVh = cvta_s(Vhi), sVl = cvta_s(Vlo);
    float acc[2][4][4];
    ZERO_ACC44(acc);
#pragma unroll
    for (int ks = 0; ks < 8; ++ks) {
        uint32_t ah[2][4], al[2][4], bh[4][2], bl[4][2];
        load_at<272>(sVh, m0, ks * 16, lane, ah);
        load_at<272>(sVl, m0, ks * 16, lane, al);
        load_wfB(0, ks, n16a, lane, bh);
        load_wfB(1, ks, n16a, lane, bl);
        mma8(acc, ah, bh);
        mma8(acc, ah, bl);
        mma8(acc, al, bh);
    }
    float* Ob = out + ((size_t)bi * 256 + j0g) * 128;
#pragma unroll
    for (int fm = 0; fm < 2; ++fm)
#pragma unroll
        for (int fn = 0; fn < 4; ++fn)
#pragma unroll
            for (int cp = 0; cp < 2; ++cp) {
                int row = m0 + fm * 16 + (lane >> 2) + cp * 8;
                int col = n0 + fn * 8 + ((lane & 3) << 1);
                *(float2*)&Ob[(size_t)row * 128 + col] =
                    make_float2(acc[fm][fn][2 * cp], acc[fm][fn][2 * cp + 1]);
            }
}

extern "C" void kernel_launch(void* const* d_in, const int* in_sizes, int n_in,
                              void* d_out, int out_size) {
    const float* x    = (const float*)d_in[0];
    const float* mask = (const float*)d_in[1];
    const float* nw   = (const float*)d_in[2];
    const float* nb   = (const float*)d_in[3];
    const float* wl   = (const float*)d_in[4];
    const float* wr   = (const float*)d_in[5];
    const float* wlg  = (const float*)d_in[6];
    const float* wrg  = (const float*)d_in[7];
    const float* wog  = (const float*)d_in[8];
    const float* onw  = (const float*)d_in[9];
    const float* onb  = (const float*)d_in[10];
    const float* wout = (const float*)d_in[11];
    float* out = (float*)d_out;

    static bool attr_done = false;
    if (!attr_done) {
        cudaFuncSetAttribute(k1_proj, cudaFuncAttributeMaxDynamicSharedMemorySize, K1_SMEM);
        cudaFuncSetAttribute(k2_tri, cudaFuncAttributeMaxDynamicSharedMemorySize, K2_SMEM);
        cudaFuncSetAttribute(k3_out, cudaFuncAttributeMaxDynamicSharedMemorySize, K3_SMEM);
        attr_done = true;
    }
    k0_prep<<<12, 256>>>(wl, wr, wlg, wrg, wog, wout);
    k1_proj<<<dim3(2, 512), 512, K1_SMEM>>>(x, mask, nw, nb);
    k2_tri<<<dim3(2, 256), 512, K2_SMEM>>>();
    k3_out<<<dim3(2, 512), 512, K3_SMEM>>>(onw, onb, out);
}

// round 17
// speedup vs baseline: 2.4404x; 1.0761x over previous
#include <cuda_runtime.h>
#include <cuda_bf16.h>
#include <cuda_fp16.h>
#include <cstdint>
#include <math.h>

using bf16 = __nv_bfloat16;
#define BB 2
#define SSZ 256

// scratch (device globals; no cudaMalloc allowed)
__device__ bf16   g_left [(size_t)BB * 128 * SSZ * SSZ];  // [b][h][i][k]
__device__ bf16   g_right[(size_t)BB * 128 * SSZ * SSZ];  // [b][h][j][k]
__device__ bf16   g_tri  [(size_t)BB * 128 * SSZ * SSZ];  // [b][h][i][j]
__device__ __half g_gate [(size_t)BB * SSZ * SSZ * 128];  // [b][i][h][j] fp16
// pre-fragmented weights (ldmatrix-equivalent layout)
__device__ uint32_t g_wfA[5][2][8][8][32][4];  // [mat][term][ks][m16][lane][q]
__device__ uint32_t g_wfB[2][8][8][32][4];     // w_out B-frags [term][ks][n16][lane][q]

static __device__ __forceinline__ uint32_t cvta_s(const void* p) {
    return (uint32_t)__cvta_generic_to_shared(p);
}
static __device__ __forceinline__ void ldsm4(uint32_t a, uint32_t& r0, uint32_t& r1,
                                             uint32_t& r2, uint32_t& r3) {
    asm volatile("ldmatrix.sync.aligned.m8n8.x4.shared.b16 {%0,%1,%2,%3},[%4];"
                 : "=r"(r0), "=r"(r1), "=r"(r2), "=r"(r3) : "r"(a));
}
static __device__ __forceinline__ void ldsm4t(uint32_t a, uint32_t& r0, uint32_t& r1,
                                              uint32_t& r2, uint32_t& r3) {
    asm volatile("ldmatrix.sync.aligned.m8n8.x4.trans.shared.b16 {%0,%1,%2,%3},[%4];"
                 : "=r"(r0), "=r"(r1), "=r"(r2), "=r"(r3) : "r"(a));
}
static __device__ __forceinline__ void mma16816(float* c, const uint32_t* a,
                                                const uint32_t* b) {
    asm volatile(
        "mma.sync.aligned.m16n8k16.row.col.f32.bf16.bf16.f32 "
        "{%0,%1,%2,%3},{%4,%5,%6,%7},{%8,%9},{%0,%1,%2,%3};"
        : "+f"(c[0]), "+f"(c[1]), "+f"(c[2]), "+f"(c[3])
        : "r"(a[0]), "r"(a[1]), "r"(a[2]), "r"(a[3]), "r"(b[0]), "r"(b[1]));
}
static __device__ __forceinline__ void cpa16(uint32_t d, const void* s) {
    asm volatile("cp.async.cg.shared.global [%0], [%1], 16;" :: "r"(d), "l"(s));
}
#define CPA_COMMIT() asm volatile("cp.async.commit_group;" ::: "memory")
#define CPA_WAIT(n) asm volatile("cp.async.wait_group %0;" :: "n"(n) : "memory")

template <int SB>  // A operand from [m][k] rows, 32 m-rows (2 frags)
static __device__ __forceinline__ void load_a(uint32_t base, int m0, int k0, int lane,
                                              uint32_t a[2][4]) {
#pragma unroll
    for (int fm = 0; fm < 2; ++fm) {
        int row = m0 + fm * 16 + (lane & 15), col = k0 + ((lane >> 4) << 3);
        ldsm4(base + row * SB + col * 2, a[fm][0], a[fm][1], a[fm][2], a[fm][3]);
    }
}
template <int SB>  // A from transposed storage [k][m] (ldmatrix.trans), 32 m-cols
static __device__ __forceinline__ void load_at(uint32_t base, int m0, int k0, int lane,
                                               uint32_t a[2][4]) {
#pragma unroll
    for (int fm = 0; fm < 2; ++fm) {
        int row = k0 + (lane & 7) + ((lane >> 4) << 3);
        int col = m0 + fm * 16 + (lane & 8);
        ldsm4t(base + row * SB + col * 2, a[fm][0], a[fm][1], a[fm][2], a[fm][3]);
    }
}
template <int SB>  // B operand, 64 n-rows (8 frags)
static __device__ __forceinline__ void load_b(uint32_t base, int n0, int k0, int lane,
                                              uint32_t b[8][2]) {
#pragma unroll
    for (int q = 0; q < 4; ++q) {
        int row = n0 + q * 16 + (lane & 7) + ((lane >> 4) << 3);
        int col = k0 + (((lane >> 3) & 1) << 3);
        ldsm4(base + row * SB + col * 2, b[2 * q][0], b[2 * q][1],
              b[2 * q + 1][0], b[2 * q + 1][1]);
    }
}
template <int SB>  // B operand, 32 n-rows (4 frags)
static __device__ __forceinline__ void load_b32(uint32_t base, int n0, int k0, int lane,
                                                uint32_t b[4][2]) {
#pragma unroll
    for (int q = 0; q < 2; ++q) {
        int row = n0 + q * 16 + (lane & 7) + ((lane >> 4) << 3);
        int col = k0 + (((lane >> 3) & 1) << 3);
        ldsm4(base + row * SB + col * 2, b[2 * q][0], b[2 * q][1],
              b[2 * q + 1][0], b[2 * q + 1][1]);
    }
}
static __device__ __forceinline__ void mma8(float acc[2][4][4], const uint32_t a[2][4],
                                            const uint32_t b[4][2]) {
#pragma unroll
    for (int fm = 0; fm < 2; ++fm)
#pragma unroll
        for (int fn = 0; fn < 4; ++fn) mma16816(acc[fm][fn], a[fm], b[fn]);
}
static __device__ __forceinline__ void load_wfA(int mat, int term, int ks, int m16a,
                                                int lane, uint32_t a[2][4]) {
    uint4 p0 = *(const uint4*)&g_wfA[mat][term][ks][m16a][lane][0];
    uint4 p1 = *(const uint4*)&g_wfA[mat][term][ks][m16a + 1][lane][0];
    a[0][0] = p0.x; a[0][1] = p0.y; a[0][2] = p0.z; a[0][3] = p0.w;
    a[1][0] = p1.x; a[1][1] = p1.y; a[1][2] = p1.z; a[1][3] = p1.w;
}
static __device__ __forceinline__ void load_wfB(int term, int ks, int n16a, int lane,
                                                uint32_t b[4][2]) {
#pragma unroll
    for (int q2 = 0; q2 < 2; ++q2) {
        uint4 w = *(const uint4*)&g_wfB[term][ks][n16a + q2][lane][0];
        b[2 * q2][0] = w.x; b[2 * q2][1] = w.y;
        b[2 * q2 + 1][0] = w.z; b[2 * q2 + 1][1] = w.w;
    }
}
static __device__ __forceinline__ float warpsum(float v) {
#pragma unroll
    for (int o = 16; o > 0; o >>= 1) v += __shfl_xor_sync(0xffffffffu, v, o);
    return v;
}
static __device__ __forceinline__ float sigmoidf_(float g) {
    return 1.0f / (1.0f + __expf(-g));
}
#define ZERO_ACC44(acc)                                         \
    {                                                           \
        _Pragma("unroll") for (int z1 = 0; z1 < 2; ++z1)        \
            _Pragma("unroll") for (int z2 = 0; z2 < 4; ++z2)    \
                _Pragma("unroll") for (int z3 = 0; z3 < 4; ++z3)\
                    acc[z1][z2][z3] = 0.f;                      \
    }

// ---------------- K0: pack weights into mma fragment layout ----------------
__global__ void k0_prep(const float* wl, const float* wr, const float* wlg,
                        const float* wrg, const float* wog, const float* wout) {
    const float* srcsA[5] = {wl, wr, wlg, wrg, wog};
    int bx = blockIdx.x;
    bool isB = bx >= 10;
    const float* src = isB ? wout : srcsA[bx >> 1];
    int term = isB ? (bx - 10) : (bx & 1);
    for (int idx = threadIdx.x; idx < 8192; idx += 256) {
        int ks = idx >> 10, rem = idx & 1023;
        int g16 = rem >> 7, rem2 = rem & 127;
        int lane = rem2 >> 2, q = rem2 & 3;
        int row, col;
        if (!isB) {
            row = g16 * 16 + (lane >> 2) + (q & 1) * 8;
            col = ks * 16 + 2 * (lane & 3) + (q >> 1) * 8;
        } else {
            row = g16 * 16 + (lane >> 2) + (q >> 1) * 8;
            col = ks * 16 + 2 * (lane & 3) + (q & 1) * 8;
        }
        float v0 = src[row * 128 + col], v1 = src[row * 128 + col + 1];
        bf16 o0, o1;
        if (term == 0) { o0 = __float2bfloat16(v0); o1 = __float2bfloat16(v1); }
        else {
            o0 = __float2bfloat16(v0 - __bfloat162float(__float2bfloat16(v0)));
            o1 = __float2bfloat16(v1 - __bfloat162float(__float2bfloat16(v1)));
        }
        __nv_bfloat162 pk(o0, o1);
        uint32_t word = *(uint32_t*)&pk;
        if (!isB) g_wfA[bx >> 1][term][ks][g16][lane][q] = word;
        else      g_wfB[term][ks][g16][lane][q] = word;
    }
}

// ---------------- K1: LN + 5 projections + gating (k-tile 64, 2 CTAs/SM) ------
// grid (4 kt, 512 bi), 256 thr. Warp tile 32x32: 4m(out_ch) x 2n(k).
#define K1_SMEM (2 * 64 * 136 * 2 + 512)
__global__ void __launch_bounds__(256, 2)
k1_proj(const float* __restrict__ x, const float* __restrict__ mask,
        const float* __restrict__ nw, const float* __restrict__ nb) {
    extern __shared__ char sm[];
    bf16* Ahi = (bf16*)sm;           // Xn_hi [k=64][d=128] stride 136
    bf16* Alo = Ahi + 64 * 136;      // Xn_lo
    float* msk = (float*)(sm + 2 * 64 * 136 * 2);
    const int tid = threadIdx.x, lane = tid & 31, wid = tid >> 5;
    const int kt = blockIdx.x, bi = blockIdx.y;
    const int b = bi >> 8, i = bi & 255, k0g = kt * 64;

    if (tid < 64) msk[tid] = mask[(size_t)bi * 256 + k0g + tid];
    const float4 nwv = reinterpret_cast<const float4*>(nw)[lane];
    const float4 nbv = reinterpret_cast<const float4*>(nb)[lane];
    for (int r = wid * 8; r < wid * 8 + 8; ++r) {
        const float4 v = reinterpret_cast<const float4*>(
            x + ((size_t)bi * 256 + k0g + r) * 128)[lane];
        float mu = warpsum(v.x + v.y + v.z + v.w) * 0.0078125f;
        float dx = v.x - mu, dy = v.y - mu, dz = v.z - mu, dw = v.w - mu;
        float rs = rsqrtf(warpsum(dx * dx + dy * dy + dz * dz + dw * dw) * 0.0078125f + 1e-5f);
        float f0 = dx * rs * nwv.x + nbv.x, f1 = dy * rs * nwv.y + nbv.y;
        float f2 = dz * rs * nwv.z + nbv.z, f3 = dw * rs * nwv.w + nbv.w;
        bf16 h0 = __float2bfloat16(f0), h1 = __float2bfloat16(f1);
        bf16 h2 = __float2bfloat16(f2), h3 = __float2bfloat16(f3);
        __nv_bfloat162* ph = (__nv_bfloat162*)(Ahi + r * 136 + lane * 4);
        ph[0] = __nv_bfloat162(h0, h1);
        ph[1] = __nv_bfloat162(h2, h3);
        __nv_bfloat162* pl = (__nv_bfloat162*)(Alo + r * 136 + lane * 4);
        pl[0] = __nv_bfloat162(__float2bfloat16(f0 - __bfloat162float(h0)),
                               __float2bfloat16(f1 - __bfloat162float(h1)));
        pl[1] = __nv_bfloat162(__float2bfloat16(f2 - __bfloat162float(h2)),
                               __float2bfloat16(f3 - __bfloat162float(h3)));
    }
    __syncthreads();
    const uint32_t sAh = cvta_s(Ahi), sAl = cvta_s(Alo);
    const int wm = wid >> 1, wn = wid & 1;  // 4m x 2n
    const int m0 = wm * 32, n0 = wn * 32, m16a = wm * 2;

#pragma unroll 1
    for (int pass = 0; pass < 2; ++pass) {
        const int mat = pass, gmat = 2 + pass;
        float accP[2][4][4], accG[2][4][4];
        ZERO_ACC44(accP); ZERO_ACC44(accG);
#pragma unroll
        for (int ks = 0; ks < 8; ++ks) {
            uint32_t bh[4][2], bl[4][2], a0[2][4], a1[2][4];
            load_b32<272>(sAh, n0, ks * 16, lane, bh);
            load_b32<272>(sAl, n0, ks * 16, lane, bl);
            load_wfA(mat, 0, ks, m16a, lane, a0);
            load_wfA(mat, 1, ks, m16a, lane, a1);
            mma8(accP, a0, bh);
            mma8(accP, a1, bh);
            mma8(accP, a0, bl);
            load_wfA(gmat, 0, ks, m16a, lane, a0);
            load_wfA(gmat, 1, ks, m16a, lane, a1);
            mma8(accG, a0, bh);
            mma8(accG, a1, bh);
            mma8(accG, a0, bl);
        }
        bf16* dst = pass == 0 ? g_left : g_right;
#pragma unroll
        for (int fm = 0; fm < 2; ++fm)
#pragma unroll
            for (int fn = 0; fn < 4; ++fn)
#pragma unroll
                for (int cp = 0; cp < 2; ++cp) {
                    int row = m0 + fm * 16 + (lane >> 2) + cp * 8;  // out_ch h
                    int col = n0 + fn * 8 + ((lane & 3) << 1);      // k (0..63)
                    float2 mk = *(float2*)(msk + col);
                    float v0 = accP[fm][fn][2 * cp] * mk.x * sigmoidf_(accG[fm][fn][2 * cp]);
                    float v1 = accP[fm][fn][2 * cp + 1] * mk.y *
                               sigmoidf_(accG[fm][fn][2 * cp + 1]);
                    *(__nv_bfloat162*)&dst[(((size_t)b * 128 + row) * 256 + i) * 256 +
                                           k0g + col] = __floats2bfloat162_rn(v0, v1);
                }
    }
    // out-gate pass (3-term), store fp16 sigmoid -> g_gate[b][i][h][j]
    {
        float accG[2][4][4];
        ZERO_ACC44(accG);
#pragma unroll
        for (int ks = 0; ks < 8; ++ks) {
            uint32_t bh[4][2], bl[4][2], a0[2][4], a1[2][4];
            load_b32<272>(sAh, n0, ks * 16, lane, bh);
            load_b32<272>(sAl, n0, ks * 16, lane, bl);
            load_wfA(4, 0, ks, m16a, lane, a0);
            load_wfA(4, 1, ks, m16a, lane, a1);
            mma8(accG, a0, bh);
            mma8(accG, a1, bh);
            mma8(accG, a0, bl);
        }
#pragma unroll
        for (int fm = 0; fm < 2; ++fm)
#pragma unroll
            for (int fn = 0; fn < 4; ++fn)
#pragma unroll
                for (int cp = 0; cp < 2; ++cp) {
                    int row = m0 + fm * 16 + (lane >> 2) + cp * 8;
                    int col = n0 + fn * 8 + ((lane & 3) << 1);
                    *(__half2*)&g_gate[((size_t)bi * 128 + row) * 256 + k0g + col] =
                        __floats2half2_rn(sigmoidf_(accG[fm][fn][2 * cp]),
                                          sigmoidf_(accG[fm][fn][2 * cp + 1]));
                }
    }
}

// ---------------- K2: batched 256^3 bf16 NT GEMM, cp.async double-buffered -------
#define K2_BUFELEM 27648
#define K2_SMEM (2 * K2_BUFELEM * 2)
__global__ void __launch_bounds__(512, 1) k2_tri() {
    extern __shared__ char sm[];
    const uint32_t sbase = cvta_s(sm);
    const int tid = threadIdx.x, lane = tid & 31, wid = tid >> 5;
    const int wm = wid & 3, wn = wid >> 2;  // 4x32 m, 4x64 n
    const int p = blockIdx.y, ti = blockIdx.x;
    const bf16* Lg = g_left + (size_t)p * 65536 + (size_t)ti * 32768;
    const bf16* Rg = g_right + (size_t)p * 65536;

    float acc[2][8][4];
#pragma unroll
    for (int z1 = 0; z1 < 2; ++z1)
#pragma unroll
        for (int z2 = 0; z2 < 8; ++z2)
#pragma unroll
            for (int z3 = 0; z3 < 4; ++z3) acc[z1][z2][z3] = 0.f;

#define K2_LOAD(c, buf)                                                       \
    {                                                                         \
        uint32_t aB = sbase + (buf) * (K2_BUFELEM * 2);                       \
        uint32_t bB = aB + 9216 * 2;                                          \
        _Pragma("unroll") for (int it = 0; it < 2; ++it) {                    \
            int idx = it * 512 + tid, r = idx >> 3, c8 = (idx & 7) << 3;      \
            cpa16(aB + (r * 72 + c8) * 2, Lg + r * 256 + (c) * 64 + c8);      \
        }                                                                     \
        _Pragma("unroll") for (int it = 0; it < 4; ++it) {                    \
            int idx = it * 512 + tid, r = idx >> 3, c8 = (idx & 7) << 3;      \
            cpa16(bB + (r * 72 + c8) * 2, Rg + r * 256 + (c) * 64 + c8);      \
        }                                                                     \
    }

    K2_LOAD(0, 0); CPA_COMMIT();
#pragma unroll 1
    for (int c = 0; c < 4; ++c) {
        if (c < 3) { K2_LOAD(c + 1, (c + 1) & 1); CPA_COMMIT(); CPA_WAIT(1); }
        else { CPA_WAIT(0); }
        __syncthreads();
        uint32_t sA = sbase + (c & 1) * (K2_BUFELEM * 2);
        uint32_t sB = sA + 9216 * 2;
#pragma unroll
        for (int ks = 0; ks < 4; ++ks) {
            uint32_t a[2][4], b[8][2];
            load_a<144>(sA, wm * 32, ks * 16, lane, a);
            load_b<144>(sB, wn * 64, ks * 16, lane, b);
#pragma unroll
            for (int fm = 0; fm < 2; ++fm)
#pragma unroll
                for (int fn = 0; fn < 8; ++fn) mma16816(acc[fm][fn], a[fm], b[fn]);
        }
        __syncthreads();
    }
#undef K2_LOAD
    bf16* Og = g_tri + (size_t)p * 65536 + (size_t)ti * 32768;
#pragma unroll
    for (int fm = 0; fm < 2; ++fm)
#pragma unroll
        for (int fn = 0; fn < 8; ++fn)
#pragma unroll
            for (int cp = 0; cp < 2; ++cp) {
                int row = wm * 32 + fm * 16 + (lane >> 2) + cp * 8;
                int col = wn * 64 + fn * 8 + ((lane & 3) << 1);
                *(__nv_bfloat162*)&Og[(size_t)row * 256 + col] =
                    __floats2bfloat162_rn(acc[fm][fn][2 * cp], acc[fm][fn][2 * cp + 1]);
            }
}

// ---------------- K3: LN over h + gate + fused 3-term GEMM (j-tile 64) ----------
// grid (4 jt, 512 bi), 256 thr, 2 CTAs/SM. Warp tile 32x32: 2m(j) x 4n(dim).
#define K3_SMEM (2 * 128 * 72 * 2 + 2 * 8 * 68 * 4 + 768)
__global__ void __launch_bounds__(256, 2)
k3_out(const float* __restrict__ onw, const float* __restrict__ onb,
       float* __restrict__ out) {
    extern __shared__ char sm[];
    bf16* Vhi = (bf16*)sm;             // [h=128][j=64] stride 72
    bf16* Vlo = Vhi + 128 * 72;
    float* red1 = (float*)(sm + 2 * 128 * 72 * 2);   // [8][68]
    float* red2 = red1 + 8 * 68;
    float* smu = red2 + 8 * 68;                      // [64]
    float* srs = smu + 64;
    const int tid = threadIdx.x, lane = tid & 31, wid = tid >> 5;
    const int jt = blockIdx.x, bi = blockIdx.y;
    const int b = bi >> 8, i = bi & 255, j0g = jt * 64;

#pragma unroll
    for (int it = 0; it < 4; ++it) {
        int idx = it * 256 + tid, h = idx >> 3, c8 = (idx & 7) << 3;
        *(uint4*)(Vhi + h * 72 + c8) =
            *(const uint4*)&g_tri[(((size_t)b * 128 + h) * 256 + i) * 256 + j0g + c8];
    }
    __syncthreads();
    // LN stats over h: each warp covers 16 h-rows; lane covers j-pair 2*lane
    {
        float s1[2] = {0.f, 0.f}, s2[2] = {0.f, 0.f};
#pragma unroll
        for (int r = 0; r < 16; ++r) {
            int h = wid * 16 + r;
            uint32_t raw = *(const uint32_t*)(Vhi + h * 72 + 2 * lane);
            float2 p0 = __bfloat1622float2(*(__nv_bfloat162*)&raw);
            s1[0] += p0.x; s2[0] += p0.x * p0.x;
            s1[1] += p0.y; s2[1] += p0.y * p0.y;
        }
        *(float2*)(red1 + wid * 68 + 2 * lane) = make_float2(s1[0], s1[1]);
        *(float2*)(red2 + wid * 68 + 2 * lane) = make_float2(s2[0], s2[1]);
    }
    __syncthreads();
    if (tid < 64) {
        float a = 0.f, c = 0.f;
#pragma unroll
        for (int w = 0; w < 8; ++w) { a += red1[w * 68 + tid]; c += red2[w * 68 + tid]; }
        float mu = a * 0.0078125f;
        float var = c * 0.0078125f - mu * mu;
        smu[tid] = mu;
        srs[tid] = rsqrtf(fmaxf(var, 0.f) + 1e-5f);
    }
    __syncthreads();
    // normalize + gate, in place, hi/lo split
    {
        const float2 mu2 = *(const float2*)(smu + 2 * lane);
        const float2 rs2 = *(const float2*)(srs + 2 * lane);
#pragma unroll
        for (int r = 0; r < 16; ++r) {
            int h = wid * 16 + r;
            float wn_ = __ldg(onw + h), bb_ = __ldg(onb + h);
            uint32_t graw =
                *(const uint32_t*)&g_gate[((size_t)bi * 128 + h) * 256 + j0g + 2 * lane];
            float2 ga = __half22float2(*(__half2*)&graw);
            uint32_t raw = *(const uint32_t*)(Vhi + h * 72 + 2 * lane);
            float2 p0 = __bfloat1622float2(*(__nv_bfloat162*)&raw);
            float v0 = ((p0.x - mu2.x) * rs2.x * wn_ + bb_) * ga.x;
            float v1 = ((p0.y - mu2.y) * rs2.y * wn_ + bb_) * ga.y;
            __nv_bfloat162 h0 = __floats2bfloat162_rn(v0, v1);
            float2 q0 = __bfloat1622float2(h0);
            *(__nv_bfloat162*)(Vhi + h * 72 + 2 * lane) = h0;
            *(__nv_bfloat162*)(Vlo + h * 72 + 2 * lane) =
                __floats2bfloat162_rn(v0 - q0.x, v1 - q0.y);
        }
    }
    __syncthreads();
    // Fused 3-term GEMM: out[j][dim] = Vhi*Whi^T + Vhi*Wlo^T + Vlo*Whi^T
    const int wm = wid & 1, wn = wid >> 1;  // 2m(j) x 4n(dim)
    const int m0 = wm * 32, n0 = wn * 32, n16a = wn * 2;
    const uint32_t sVh = cvta_s(Vhi), sVl = cvta_s(Vlo);
    float acc[2][4][4];
    ZERO_ACC44(acc);
#pragma unroll
    for (int ks = 0; ks < 8; ++ks) {
        uint32_t ah[2][4], al[2][4], bh[4][2], bl[4][2];
        load_at<144>(sVh, m0, ks * 16, lane, ah);
        load_at<144>(sVl, m0, ks * 16, lane, al);
        load_wfB(0, ks, n16a, lane, bh);
        load_wfB(1, ks, n16a, lane, bl);
        mma8(acc, ah, bh);
        mma8(acc, ah, bl);
        mma8(acc, al, bh);
    }
    float* Ob = out + ((size_t)bi * 256 + j0g) * 128;
#pragma unroll
    for (int fm = 0; fm < 2; ++fm)
#pragma unroll
        for (int fn = 0; fn < 4; ++fn)
#pragma unroll
            for (int cp = 0; cp < 2; ++cp) {
                int row = m0 + fm * 16 + (lane >> 2) + cp * 8;  // j (0..63)
                int col = n0 + fn * 8 + ((lane & 3) << 1);      // dim
                *(float2*)&Ob[(size_t)row * 128 + col] =
                    make_float2(acc[fm][fn][2 * cp], acc[fm][fn][2 * cp + 1]);
            }
}

extern "C" void kernel_launch(void* const* d_in, const int* in_sizes, int n_in,
                              void* d_out, int out_size) {
    const float* x    = (const float*)d_in[0];
    const float* mask = (const float*)d_in[1];
    const float* nw   = (const float*)d_in[2];
    const float* nb   = (const float*)d_in[3];
    const float* wl   = (const float*)d_in[4];
    const float* wr   = (const float*)d_in[5];
    const float* wlg  = (const float*)d_in[6];
    const float* wrg  = (const float*)d_in[7];
    const float* wog  = (const float*)d_in[8];
    const float* onw  = (const float*)d_in[9];
    const float* onb  = (const float*)d_in[10];
    const float* wout = (const float*)d_in[11];
    float* out = (float*)d_out;

    static bool attr_done = false;
    if (!attr_done) {
        cudaFuncSetAttribute(k1_proj, cudaFuncAttributeMaxDynamicSharedMemorySize, K1_SMEM);
        cudaFuncSetAttribute(k2_tri, cudaFuncAttributeMaxDynamicSharedMemorySize, K2_SMEM);
        cudaFuncSetAttribute(k3_out, cudaFuncAttributeMaxDynamicSharedMemorySize, K3_SMEM);
        attr_done = true;
    }
    k0_prep<<<12, 256>>>(wl, wr, wlg, wrg, wog, wout);
    k1_proj<<<dim3(4, 512), 256, K1_SMEM>>>(x, mask, nw, nb);
    k2_tri<<<dim3(2, 256), 512, K2_SMEM>>>();
    k3_out<<<dim3(4, 512), 256, K3_SMEM>>>(onw, onb, out);
}